// round 3
// baseline (speedup 1.0000x reference)
#include <cuda_runtime.h>
#include <math.h>

// Problem dims
#define Tn 128
#define Bn 512
#define Dn 1024
#define Hn 128
#define G4 512   // 4*H

// -------- scratch (device globals: no allocations allowed) --------
__device__ float g_pre[(size_t)Tn * Bn * G4];   // [t][b][4H]  (134 MB)
__device__ float g_h1[2 * Bn * Hn];             // ping-pong
__device__ float g_c1[Bn * Hn];
__device__ float g_h2[2 * Bn * Hn];             // ping-pong
__device__ float g_c2[Bn * Hn];

// -------- zero initial state (h1[0], c1, h2[0], c2) --------
__global__ void zero_state() {
    int i = blockIdx.x * blockDim.x + threadIdx.x;
    if (i < Bn * Hn) {
        g_h1[i] = 0.f;
        g_c1[i] = 0.f;
        g_h2[i] = 0.f;
        g_c2[i] = 0.f;
    }
}

// -------- big input GEMM: pre[t][b][:] = feats_row(m) @ Wih1^T + bih1 + bhh1 --------
// feats is [B][T][D] row-major => flat [65536][1024] with m = b*T + t.
// Classic 128x128 tile, BK=8, 256 threads, 8x8 per thread.
__global__ void __launch_bounds__(256) gemm_pre(
    const float* __restrict__ A,     // [65536][1024]
    const float* __restrict__ W,     // [512][1024]
    const float* __restrict__ b1,    // [512]
    const float* __restrict__ b2,    // [512]
    float* __restrict__ out)         // [T][B][512]
{
    __shared__ float As[8][128];
    __shared__ float Bs[8][128];

    const int tid = threadIdx.x;
    const int m0 = blockIdx.x * 128;
    const int n0 = blockIdx.y * 128;

    const int lrow = tid >> 1;          // 0..127
    const int lk4  = (tid & 1) * 4;     // 0 or 4

    const float* Ag = A + (size_t)(m0 + lrow) * Dn + lk4;
    const float* Wg = W + (size_t)(n0 + lrow) * Dn + lk4;

    const int ty = tid >> 4;            // 0..15
    const int tx = tid & 15;            // 0..15

    float acc[8][8];
#pragma unroll
    for (int i = 0; i < 8; i++)
#pragma unroll
        for (int j = 0; j < 8; j++) acc[i][j] = 0.f;

    for (int k0 = 0; k0 < Dn; k0 += 8) {
        float4 av = *(const float4*)(Ag + k0);
        float4 wv = *(const float4*)(Wg + k0);
        As[lk4 + 0][lrow] = av.x;
        As[lk4 + 1][lrow] = av.y;
        As[lk4 + 2][lrow] = av.z;
        As[lk4 + 3][lrow] = av.w;
        Bs[lk4 + 0][lrow] = wv.x;
        Bs[lk4 + 1][lrow] = wv.y;
        Bs[lk4 + 2][lrow] = wv.z;
        Bs[lk4 + 3][lrow] = wv.w;
        __syncthreads();

#pragma unroll
        for (int k = 0; k < 8; k++) {
            float a[8], b[8];
            *(float4*)(a)     = *(const float4*)&As[k][ty * 8];
            *(float4*)(a + 4) = *(const float4*)&As[k][ty * 8 + 4];
            *(float4*)(b)     = *(const float4*)&Bs[k][tx * 8];
            *(float4*)(b + 4) = *(const float4*)&Bs[k][tx * 8 + 4];
#pragma unroll
            for (int i = 0; i < 8; i++)
#pragma unroll
                for (int j = 0; j < 8; j++)
                    acc[i][j] += a[i] * b[j];
        }
        __syncthreads();
    }

    // epilogue: m -> (b = m>>7, t = m&127); out[t][b][n] = acc + b1[n] + b2[n]
#pragma unroll
    for (int i = 0; i < 8; i++) {
        int m = m0 + ty * 8 + i;
        int tt = m & (Tn - 1);
        int bb = m >> 7;
        float* orow = out + ((size_t)tt * Bn + bb) * G4 + n0 + tx * 8;
#pragma unroll
        for (int j = 0; j < 8; j += 4) {
            int n = n0 + tx * 8 + j;
            float4 v;
            v.x = acc[i][j + 0] + b1[n + 0] + b2[n + 0];
            v.y = acc[i][j + 1] + b1[n + 1] + b2[n + 1];
            v.z = acc[i][j + 2] + b1[n + 2] + b2[n + 2];
            v.w = acc[i][j + 3] + b1[n + 3] + b2[n + 3];
            *(float4*)(orow + j) = v;
        }
    }
}

__device__ __forceinline__ float sigf(float x) { return 1.f / (1.f + expf(-x)); }

// -------- layer-1 cell step --------
// grid (32, 4): blockIdx.x = batch block (16 rows), blockIdx.y = unit block (32 units)
// Each thread t computes one gate column c = t (gate g = t/32, unit u = t%32) for 16 batch rows.
__global__ void __launch_bounds__(128) lstm_l1(
    const float* __restrict__ pre_t,   // [B][512] slice for this step (includes both biases)
    const float* __restrict__ hprev,   // [B][H]
    const float* __restrict__ W,       // Whh1 [512][128]
    float* __restrict__ hnew,          // [B][H]
    float* __restrict__ c)             // [B][H] in-place
{
    __shared__ float hs[16 * 128];
    __shared__ float G[4 * 32 * 17];   // [gate][unit][batch], padded

    const int bb = blockIdx.x;
    const int ub = blockIdx.y;
    const int t  = threadIdx.x;

    // load h block (16x128) into smem
    {
        const float4* hp4 = (const float4*)(hprev + (size_t)bb * 16 * Hn);
        float4* hs4 = (float4*)hs;
#pragma unroll
        for (int i = 0; i < 4; i++) hs4[t + i * 128] = hp4[t + i * 128];
    }
    __syncthreads();

    const int g = t >> 5;
    const int u = t & 31;
    const int gcol = g * 128 + ub * 32 + u;
    const float4* wrow = (const float4*)(W + (size_t)gcol * Hn);

    float acc[16];
#pragma unroll
    for (int b = 0; b < 16; b++) acc[b] = 0.f;

#pragma unroll 4
    for (int k4 = 0; k4 < 32; k4++) {
        float4 wv = wrow[k4];
#pragma unroll
        for (int b = 0; b < 16; b++) {
            float4 hv = *(const float4*)&hs[b * 128 + k4 * 4];
            acc[b] += wv.x * hv.x + wv.y * hv.y + wv.z * hv.z + wv.w * hv.w;
        }
    }

#pragma unroll
    for (int b = 0; b < 16; b++)
        acc[b] += pre_t[(size_t)(bb * 16 + b) * G4 + gcol];

#pragma unroll
    for (int b = 0; b < 16; b++)
        G[(g * 32 + u) * 17 + b] = acc[b];
    __syncthreads();

    // cell update: 512 (b,u) pairs, 4 per thread
#pragma unroll
    for (int i = 0; i < 4; i++) {
        int idx = t + i * 128;
        int b  = idx >> 5;
        int uu = idx & 31;
        float iv = G[(0 * 32 + uu) * 17 + b];
        float fv = G[(1 * 32 + uu) * 17 + b];
        float gv = G[(2 * 32 + uu) * 17 + b];
        float ov = G[(3 * 32 + uu) * 17 + b];
        int o = (bb * 16 + b) * Hn + ub * 32 + uu;
        float cp = c[o];
        float cn = sigf(fv) * cp + sigf(iv) * tanhf(gv);
        c[o] = cn;
        hnew[o] = sigf(ov) * tanhf(cn);
    }
}

// -------- layer-2 cell step: gates = h1 @ Wih2^T + h2 @ Whh2^T + bih2 + bhh2 --------
__global__ void __launch_bounds__(128) lstm_l2(
    const float* __restrict__ h1t,     // [B][H] (this step's layer-1 output)
    const float* __restrict__ h2prev,  // [B][H]
    const float* __restrict__ Wih,     // [512][128]
    const float* __restrict__ Whh,     // [512][128]
    const float* __restrict__ bi,      // [512]
    const float* __restrict__ bh,      // [512]
    float* __restrict__ h2new,         // [B][H] (d_out on final step)
    float* __restrict__ c)             // [B][H] in-place
{
    __shared__ float hs1[16 * 128];
    __shared__ float hs2[16 * 128];
    __shared__ float G[4 * 32 * 17];

    const int bb = blockIdx.x;
    const int ub = blockIdx.y;
    const int t  = threadIdx.x;

    {
        const float4* ha = (const float4*)(h1t + (size_t)bb * 16 * Hn);
        const float4* hb = (const float4*)(h2prev + (size_t)bb * 16 * Hn);
        float4* sa = (float4*)hs1;
        float4* sb = (float4*)hs2;
#pragma unroll
        for (int i = 0; i < 4; i++) {
            sa[t + i * 128] = ha[t + i * 128];
            sb[t + i * 128] = hb[t + i * 128];
        }
    }
    __syncthreads();

    const int g = t >> 5;
    const int u = t & 31;
    const int gcol = g * 128 + ub * 32 + u;
    const float4* wi = (const float4*)(Wih + (size_t)gcol * Hn);
    const float4* wh = (const float4*)(Whh + (size_t)gcol * Hn);

    const float bias = bi[gcol] + bh[gcol];
    float acc[16];
#pragma unroll
    for (int b = 0; b < 16; b++) acc[b] = bias;

#pragma unroll 4
    for (int k4 = 0; k4 < 32; k4++) {
        float4 wv = wi[k4];
#pragma unroll
        for (int b = 0; b < 16; b++) {
            float4 hv = *(const float4*)&hs1[b * 128 + k4 * 4];
            acc[b] += wv.x * hv.x + wv.y * hv.y + wv.z * hv.z + wv.w * hv.w;
        }
    }
#pragma unroll 4
    for (int k4 = 0; k4 < 32; k4++) {
        float4 wv = wh[k4];
#pragma unroll
        for (int b = 0; b < 16; b++) {
            float4 hv = *(const float4*)&hs2[b * 128 + k4 * 4];
            acc[b] += wv.x * hv.x + wv.y * hv.y + wv.z * hv.z + wv.w * hv.w;
        }
    }

#pragma unroll
    for (int b = 0; b < 16; b++)
        G[(g * 32 + u) * 17 + b] = acc[b];
    __syncthreads();

#pragma unroll
    for (int i = 0; i < 4; i++) {
        int idx = t + i * 128;
        int b  = idx >> 5;
        int uu = idx & 31;
        float iv = G[(0 * 32 + uu) * 17 + b];
        float fv = G[(1 * 32 + uu) * 17 + b];
        float gv = G[(2 * 32 + uu) * 17 + b];
        float ov = G[(3 * 32 + uu) * 17 + b];
        int o = (bb * 16 + b) * Hn + ub * 32 + uu;
        float cp = c[o];
        float cn = sigf(fv) * cp + sigf(iv) * tanhf(gv);
        c[o] = cn;
        h2new[o] = sigf(ov) * tanhf(cn);
    }
}

// -------- launch --------
extern "C" void kernel_launch(void* const* d_in, const int* in_sizes, int n_in,
                              void* d_out, int out_size) {
    const float* feats = (const float*)d_in[0];
    const float* Wih1  = (const float*)d_in[1];
    const float* Whh1  = (const float*)d_in[2];
    const float* bih1  = (const float*)d_in[3];
    const float* bhh1  = (const float*)d_in[4];
    const float* Wih2  = (const float*)d_in[5];
    const float* Whh2  = (const float*)d_in[6];
    const float* bih2  = (const float*)d_in[7];
    const float* bhh2  = (const float*)d_in[8];

    float *pre, *h1, *c1, *h2, *c2;
    cudaGetSymbolAddress((void**)&pre, g_pre);
    cudaGetSymbolAddress((void**)&h1,  g_h1);
    cudaGetSymbolAddress((void**)&c1,  g_c1);
    cudaGetSymbolAddress((void**)&h2,  g_h2);
    cudaGetSymbolAddress((void**)&c2,  g_c2);

    zero_state<<<(Bn * Hn + 255) / 256, 256>>>();

    // pre[t][b][:] = feats @ Wih1^T + bih1 + bhh1   (M=65536, N=512, K=1024)
    gemm_pre<<<dim3(512, 4), 256>>>(feats, Wih1, bih1, bhh1, pre);

    for (int t = 0; t < Tn; t++) {
        int p = t & 1;
        lstm_l1<<<dim3(32, 4), 128>>>(
            pre + (size_t)t * Bn * G4,
            h1 + (size_t)p * Bn * Hn,
            Whh1,
            h1 + (size_t)(1 - p) * Bn * Hn,
            c1);
        float* h2o = (t == Tn - 1) ? (float*)d_out : (h2 + (size_t)(1 - p) * Bn * Hn);
        lstm_l2<<<dim3(32, 4), 128>>>(
            h1 + (size_t)(1 - p) * Bn * Hn,
            h2 + (size_t)p * Bn * Hn,
            Wih2, Whh2, bih2, bhh2,
            h2o,
            c2);
    }
}

// round 4
// speedup vs baseline: 1.4159x; 1.4159x over previous
#include <cuda_runtime.h>
#include <math.h>

// Problem dims
#define Tn 128
#define Bn 512
#define Dn 1024
#define Hn 128
#define G4 512   // 4*H
#define BH (Bn*Hn)

#define NCTA 128   // persistent grid size

// -------- scratch (device globals: no allocations allowed) --------
__device__ float g_pre[(size_t)Tn * Bn * G4];   // [t][b][4H]
__device__ float g_h1[2 * BH];                  // ping-pong
__device__ float g_h2[2 * BH];                  // ping-pong
__device__ unsigned g_barcnt;                   // zero-init
__device__ unsigned g_bargen;                   // generation counter (monotonic)

// -------- big input GEMM: pre[t][b][:] = feats_row(m) @ Wih1^T + bih1 + bhh1 --------
__global__ void __launch_bounds__(256) gemm_pre(
    const float* __restrict__ A,     // [65536][1024]
    const float* __restrict__ W,     // [512][1024]
    const float* __restrict__ b1,    // [512]
    const float* __restrict__ b2,    // [512]
    float* __restrict__ out)         // [T][B][512]
{
    __shared__ float As[8][128];
    __shared__ float Bs[8][128];

    const int tid = threadIdx.x;
    const int m0 = blockIdx.x * 128;
    const int n0 = blockIdx.y * 128;

    const int lrow = tid >> 1;
    const int lk4  = (tid & 1) * 4;

    const float* Ag = A + (size_t)(m0 + lrow) * Dn + lk4;
    const float* Wg = W + (size_t)(n0 + lrow) * Dn + lk4;

    const int ty = tid >> 4;
    const int tx = tid & 15;

    float acc[8][8];
#pragma unroll
    for (int i = 0; i < 8; i++)
#pragma unroll
        for (int j = 0; j < 8; j++) acc[i][j] = 0.f;

    for (int k0 = 0; k0 < Dn; k0 += 8) {
        float4 av = *(const float4*)(Ag + k0);
        float4 wv = *(const float4*)(Wg + k0);
        As[lk4 + 0][lrow] = av.x;
        As[lk4 + 1][lrow] = av.y;
        As[lk4 + 2][lrow] = av.z;
        As[lk4 + 3][lrow] = av.w;
        Bs[lk4 + 0][lrow] = wv.x;
        Bs[lk4 + 1][lrow] = wv.y;
        Bs[lk4 + 2][lrow] = wv.z;
        Bs[lk4 + 3][lrow] = wv.w;
        __syncthreads();

#pragma unroll
        for (int k = 0; k < 8; k++) {
            float a[8], b[8];
            *(float4*)(a)     = *(const float4*)&As[k][ty * 8];
            *(float4*)(a + 4) = *(const float4*)&As[k][ty * 8 + 4];
            *(float4*)(b)     = *(const float4*)&Bs[k][tx * 8];
            *(float4*)(b + 4) = *(const float4*)&Bs[k][tx * 8 + 4];
#pragma unroll
            for (int i = 0; i < 8; i++)
#pragma unroll
                for (int j = 0; j < 8; j++)
                    acc[i][j] += a[i] * b[j];
        }
        __syncthreads();
    }

#pragma unroll
    for (int i = 0; i < 8; i++) {
        int m = m0 + ty * 8 + i;
        int tt = m & (Tn - 1);
        int bb = m >> 7;
        float* orow = out + ((size_t)tt * Bn + bb) * G4 + n0 + tx * 8;
#pragma unroll
        for (int j = 0; j < 8; j += 4) {
            int n = n0 + tx * 8 + j;
            float4 v;
            v.x = acc[i][j + 0] + b1[n + 0] + b2[n + 0];
            v.y = acc[i][j + 1] + b1[n + 1] + b2[n + 1];
            v.z = acc[i][j + 2] + b1[n + 2] + b2[n + 2];
            v.w = acc[i][j + 3] + b1[n + 3] + b2[n + 3];
            *(float4*)(orow + j) = v;
        }
    }
}

__device__ __forceinline__ float sigf(float x) { return 1.f / (1.f + expf(-x)); }

// -------- grid barrier (sense via generation counter) --------
__device__ __forceinline__ void grid_barrier() {
    __syncthreads();
    if (threadIdx.x == 0) {
        __threadfence();
        unsigned gen = *(volatile unsigned*)&g_bargen;   // read BEFORE arriving
        unsigned ticket = atomicAdd(&g_barcnt, 1);
        if (ticket == NCTA - 1) {
            *(volatile unsigned*)&g_barcnt = 0;
            __threadfence();
            atomicAdd(&g_bargen, 1);
        } else {
            while (*(volatile unsigned*)&g_bargen == gen) { __nanosleep(40); }
            __threadfence();
        }
    }
    __syncthreads();
}

// -------- persistent recurrent kernel --------
// Grid: 128 CTAs = 16 batch-blocks (32 rows) x 8 unit-blocks (16 units).
// SMEM float layout (all via one dynamic buffer):
//   W1t   [32][64][4]  transposed Whh1 slice     (8192 f)
//   Wi2t  [32][64][4]  transposed Wih2 slice     (8192 f)
//   Wh2t  [32][64][4]  transposed Whh2 slice     (8192 f)
//   h1s   [32][128]                              (4096 f)
//   h2s   [32][128]                              (4096 f)
//   G     [64][33]     gate staging              (2112 f)
//   c1s   [512], c2s [512], bias2 [64]
#define OFF_W1   0
#define OFF_WI2  8192
#define OFF_WH2  16384
#define OFF_H1S  24576
#define OFF_H2S  28672
#define OFF_G    32768
#define OFF_C1   34880
#define OFF_C2   35392
#define OFF_B2   35904
#define SMEM_F   35968
#define SMEM_BYTES (SMEM_F * 4)

__global__ void __launch_bounds__(256, 1) lstm_persist(
    const float* __restrict__ pre,    // [T][B][512]
    const float* __restrict__ Whh1,   // [512][128]
    const float* __restrict__ Wih2,   // [512][128]
    const float* __restrict__ Whh2,   // [512][128]
    const float* __restrict__ bih2,   // [512]
    const float* __restrict__ bhh2,   // [512]
    float* __restrict__ h2out)        // [B][128]  (d_out)
{
    extern __shared__ float sm[];
    const int tid = threadIdx.x;
    const int bb  = blockIdx.x >> 3;   // batch block 0..15
    const int ub  = blockIdx.x & 7;    // unit block  0..7

    float* W1t  = sm + OFF_W1;
    float* Wi2t = sm + OFF_WI2;
    float* Wh2t = sm + OFF_WH2;
    float* h1s  = sm + OFF_H1S;
    float* h2s  = sm + OFF_H2S;
    float* G    = sm + OFF_G;
    float* c1s  = sm + OFF_C1;
    float* c2s  = sm + OFF_C2;
    float* b2s  = sm + OFF_B2;

    // ---- init: load weight slices (transposed), biases, zero state ----
    // gatecol for local col j (0..63): (j>>4)*128 + ub*16 + (j&15)
    for (int idx = tid; idx < 64 * 128; idx += 256) {
        int j = idx >> 7;
        int k = idx & 127;
        int gcol = ((j >> 4) << 7) + (ub << 4) + (j & 15);
        int so = (k >> 2) * 256 + j * 4 + (k & 3);
        W1t[so]  = Whh1[(size_t)gcol * Hn + k];
        Wi2t[so] = Wih2[(size_t)gcol * Hn + k];
        Wh2t[so] = Whh2[(size_t)gcol * Hn + k];
    }
    if (tid < 64) {
        int gcol = ((tid >> 4) << 7) + (ub << 4) + (tid & 15);
        b2s[tid] = bih2[gcol] + bhh2[gcol];
    }
    for (int i = tid; i < 512; i += 256) { c1s[i] = 0.f; c2s[i] = 0.f; }
    // zero our tiles of h1[0], h2[0]
    {
        int u = tid & 15;
        int bl = tid >> 4;          // 0..15
#pragma unroll
        for (int i = 0; i < 2; i++) {
            int row = bb * 32 + bl + i * 16;
            int col = ub * 16 + u;
            g_h1[row * Hn + col] = 0.f;
            g_h2[row * Hn + col] = 0.f;
        }
    }
    grid_barrier();

    const int bg = tid >> 6;        // 0..3  (group of 8 batch rows)
    const int j  = tid & 63;        // local gate-column
    const int gcol = ((j >> 4) << 7) + (ub << 4) + (j & 15);
    const int u2 = tid & 15;
    const int bl0 = tid >> 4;       // 0..15

    const float4* w1 = (const float4*)W1t;
    const float4* wi2 = (const float4*)Wi2t;
    const float4* wh2 = (const float4*)Wh2t;
    const float4* h1s4 = (const float4*)h1s;
    const float4* h2s4 = (const float4*)h2s;

    for (int t = 0; t < Tn; t++) {
        const int p = t & 1;
        const float* h1cur = g_h1 + p * BH;
        float* h1next      = g_h1 + (1 - p) * BH;
        const float* h2cur = g_h2 + p * BH;
        float* h2next      = g_h2 + (1 - p) * BH;

        // ===== Phase A: layer-1 =====
        // load h1prev rows [bb*32, +32) x 128 into smem
        {
            const float4* src = (const float4*)(h1cur + (size_t)bb * 32 * Hn);
            float4* dst = (float4*)h1s;
#pragma unroll
            for (int i = 0; i < 4; i++) dst[tid + i * 256] = src[tid + i * 256];
        }
        __syncthreads();

        {
            const float* preb = pre + ((size_t)t * Bn + bb * 32 + bg * 8) * G4 + gcol;
            float acc[8];
#pragma unroll
            for (int b = 0; b < 8; b++) acc[b] = preb[b * G4];
#pragma unroll 8
            for (int k4 = 0; k4 < 32; k4++) {
                float4 wv = w1[k4 * 64 + j];
#pragma unroll
                for (int b = 0; b < 8; b++) {
                    float4 hv = h1s4[(bg * 8 + b) * 32 + k4];
                    acc[b] += wv.x * hv.x + wv.y * hv.y + wv.z * hv.z + wv.w * hv.w;
                }
            }
#pragma unroll
            for (int b = 0; b < 8; b++) G[j * 33 + bg * 8 + b] = acc[b];
        }
        __syncthreads();

        // cell update layer1 (each thread: 2 (b,u) pairs)
#pragma unroll
        for (int i = 0; i < 2; i++) {
            int bl = bl0 + i * 16;
            float iv = G[(0 * 16 + u2) * 33 + bl];
            float fv = G[(1 * 16 + u2) * 33 + bl];
            float gv = G[(2 * 16 + u2) * 33 + bl];
            float ov = G[(3 * 16 + u2) * 33 + bl];
            int ci = bl * 16 + u2;
            float cp = c1s[ci];
            float cn = sigf(fv) * cp + sigf(iv) * tanhf(gv);
            c1s[ci] = cn;
            h1next[(bb * 32 + bl) * Hn + ub * 16 + u2] = sigf(ov) * tanhf(cn);
        }
        __threadfence();
        grid_barrier();

        // ===== Phase B: layer-2 =====
        {
            const float4* s1 = (const float4*)(h1next + (size_t)bb * 32 * Hn);
            const float4* s2 = (const float4*)(h2cur + (size_t)bb * 32 * Hn);
            float4* d1 = (float4*)h1s;
            float4* d2 = (float4*)h2s;
#pragma unroll
            for (int i = 0; i < 4; i++) {
                d1[tid + i * 256] = s1[tid + i * 256];
                d2[tid + i * 256] = s2[tid + i * 256];
            }
        }
        __syncthreads();

        {
            float acc[8];
            float bias = b2s[j];
#pragma unroll
            for (int b = 0; b < 8; b++) acc[b] = bias;
#pragma unroll 8
            for (int k4 = 0; k4 < 32; k4++) {
                float4 wv = wi2[k4 * 64 + j];
#pragma unroll
                for (int b = 0; b < 8; b++) {
                    float4 hv = h1s4[(bg * 8 + b) * 32 + k4];
                    acc[b] += wv.x * hv.x + wv.y * hv.y + wv.z * hv.z + wv.w * hv.w;
                }
            }
#pragma unroll 8
            for (int k4 = 0; k4 < 32; k4++) {
                float4 wv = wh2[k4 * 64 + j];
#pragma unroll
                for (int b = 0; b < 8; b++) {
                    float4 hv = h2s4[(bg * 8 + b) * 32 + k4];
                    acc[b] += wv.x * hv.x + wv.y * hv.y + wv.z * hv.z + wv.w * hv.w;
                }
            }
#pragma unroll
            for (int b = 0; b < 8; b++) G[j * 33 + bg * 8 + b] = acc[b];
        }
        __syncthreads();

        float* h2dst = (t == Tn - 1) ? h2out : h2next;
#pragma unroll
        for (int i = 0; i < 2; i++) {
            int bl = bl0 + i * 16;
            float iv = G[(0 * 16 + u2) * 33 + bl];
            float fv = G[(1 * 16 + u2) * 33 + bl];
            float gv = G[(2 * 16 + u2) * 33 + bl];
            float ov = G[(3 * 16 + u2) * 33 + bl];
            int ci = bl * 16 + u2;
            float cp = c2s[ci];
            float cn = sigf(fv) * cp + sigf(iv) * tanhf(gv);
            c2s[ci] = cn;
            h2dst[(bb * 32 + bl) * Hn + ub * 16 + u2] = sigf(ov) * tanhf(cn);
        }
        // no end-of-step barrier needed: only concurrent pair {B(t), A(t+1)}
        // touches disjoint buffers; barrier after A(t+1) orders B(t) vs B(t+1).
        __syncthreads();
        if (t < Tn - 1) __threadfence();
    }
}

// -------- launch --------
extern "C" void kernel_launch(void* const* d_in, const int* in_sizes, int n_in,
                              void* d_out, int out_size) {
    const float* feats = (const float*)d_in[0];
    const float* Wih1  = (const float*)d_in[1];
    const float* Whh1  = (const float*)d_in[2];
    const float* bih1  = (const float*)d_in[3];
    const float* bhh1  = (const float*)d_in[4];
    const float* Wih2  = (const float*)d_in[5];
    const float* Whh2  = (const float*)d_in[6];
    const float* bih2  = (const float*)d_in[7];
    const float* bhh2  = (const float*)d_in[8];

    float* pre;
    cudaGetSymbolAddress((void**)&pre, g_pre);

    static int attr_set = 0;
    if (!attr_set) {
        cudaFuncSetAttribute(lstm_persist,
                             cudaFuncAttributeMaxDynamicSharedMemorySize,
                             SMEM_BYTES);
        attr_set = 1;
    }

    // pre[t][b][:] = feats @ Wih1^T + bih1 + bhh1   (M=65536, N=512, K=1024)
    gemm_pre<<<dim3(512, 4), 256>>>(feats, Wih1, bih1, bhh1, pre);

    lstm_persist<<<NCTA, 256, SMEM_BYTES>>>(
        pre, Whh1, Wih2, Whh2, bih2, bhh2, (float*)d_out);
}

// round 6
// speedup vs baseline: 2.0906x; 1.4765x over previous
#include <cuda_runtime.h>
#include <cuda_bf16.h>
#include <math.h>
#include <stdint.h>

// Problem dims
#define Tn 128
#define Bn 512
#define Dn 1024
#define Hn 128
#define G4 512   // 4*H
#define BH (Bn*Hn)

#define NCTA 128   // persistent grid size

// -------- scratch (device globals: no allocations allowed) --------
__device__ float g_pre[(size_t)Tn * Bn * G4];   // [t][b][4H]
__device__ float g_h1[2 * BH];                  // ping-pong
__device__ float g_h2[2 * BH];                  // ping-pong
__device__ unsigned g_barcnt;                   // zero-init
__device__ unsigned g_bargen;                   // generation counter (monotonic)

// ============================================================================
// helpers
// ============================================================================
__device__ __forceinline__ uint32_t smem_u32(const void* p) {
    uint32_t a;
    asm("{ .reg .u64 t; cvta.to.shared.u64 t, %1; cvt.u32.u64 %0, t; }"
        : "=r"(a) : "l"(p));
    return a;
}

__device__ __forceinline__ void ldsm4(uint32_t* r, uint32_t addr) {
    asm volatile("ldmatrix.sync.aligned.m8n8.x4.shared.b16 {%0,%1,%2,%3}, [%4];"
                 : "=r"(r[0]), "=r"(r[1]), "=r"(r[2]), "=r"(r[3]) : "r"(addr));
}

__device__ __forceinline__ void mma16816(float* d, const uint32_t* a, const uint32_t* b) {
    asm volatile(
        "mma.sync.aligned.m16n8k16.row.col.f32.bf16.bf16.f32 "
        "{%0,%1,%2,%3}, {%4,%5,%6,%7}, {%8,%9}, {%0,%1,%2,%3};"
        : "+f"(d[0]), "+f"(d[1]), "+f"(d[2]), "+f"(d[3])
        : "r"(a[0]), "r"(a[1]), "r"(a[2]), "r"(a[3]), "r"(b[0]), "r"(b[1]));
}

// split 8 consecutive fp32 into bf16 hi (rn) and bf16 lo = bf16(x - hi)
__device__ __forceinline__ void split8(float4 v0, float4 v1, uint4& hi, uint4& lo) {
    float f[8] = {v0.x, v0.y, v0.z, v0.w, v1.x, v1.y, v1.z, v1.w};
    uint32_t ph[4], pl[4];
#pragma unroll
    for (int j = 0; j < 4; j++) {
        float a = f[2 * j], b = f[2 * j + 1];
        uint32_t p;
        asm("cvt.rn.bf16x2.f32 %0, %1, %2;" : "=r"(p) : "f"(b), "f"(a)); // low=a, high=b
        float ha = __uint_as_float(p << 16);
        float hb = __uint_as_float(p & 0xFFFF0000u);
        float la = a - ha, lb = b - hb;
        uint32_t q;
        asm("cvt.rn.bf16x2.f32 %0, %1, %2;" : "=r"(q) : "f"(lb), "f"(la));
        ph[j] = p; pl[j] = q;
    }
    hi = make_uint4(ph[0], ph[1], ph[2], ph[3]);
    lo = make_uint4(pl[0], pl[1], pl[2], pl[3]);
}

// ============================================================================
// bf16-split mma.sync GEMM:
// pre[t][b][:] = feats_row(m) @ Wih1^T + bih1 + bhh1
// feats [65536][1024] fp32 (m = b*T + t), Wih1 [512][1024] fp32.
// 3-term split (AhBh + AhBl + AlBh) in fp32 accumulators.
// CTA tile 128x128, K-chunk 32, 8 warps of 32x64. Grid (4 n-tiles, 512 m-tiles).
// ============================================================================
__global__ void __launch_bounds__(256, 1) gemm_pre_mma(
    const float* __restrict__ A,     // [65536][1024]
    const float* __restrict__ W,     // [512][1024]
    const float* __restrict__ b1,    // [512]
    const float* __restrict__ b2,    // [512]
    float* __restrict__ out)         // [T][B][512]
{
    // smem: Ahi[128][32]bf16 @0, Alo @8192, Bhi @16384, Blo @24576 (8KB each)
    __shared__ __align__(128) char smbuf[32768];
    __shared__ float bias_s[128];

    const int tid  = threadIdx.x;
    const int lane = tid & 31;
    const int wid  = tid >> 5;
    const int n0 = blockIdx.x * 128;
    const int m0 = blockIdx.y * 128;
    const uint32_t sb = smem_u32(smbuf);

    if (tid < 128) bias_s[tid] = b1[n0 + tid] + b2[n0 + tid];

    // ---- per-thread store slots: row r, k-units u0, u0+1 (16B each) ----
    const int r   = tid >> 1;
    const int u0  = (tid & 1) * 2;
    const int ssw = (r >> 1) & 3;
    const int so0 = r * 64 + (((u0)     ^ ssw) << 4);
    const int so1 = r * 64 + (((u0 + 1) ^ ssw) << 4);

    const float4* aptr = (const float4*)(A + (size_t)(m0 + r) * Dn) + (tid & 1) * 4;
    const float4* bptr = (const float4*)(W + (size_t)(n0 + r) * Dn) + (tid & 1) * 4;

    // ---- warp tile ----
    const int m0w = (wid >> 1) * 32;
    const int n0w = (wid & 1) * 64;

    // ldmatrix lane address components
    const int rowA = m0w + (lane & 15);
    const int jA   = lane >> 4;                 // k-unit select within kf
    const int swA  = (rowA >> 1) & 3;
    const uint32_t aAh = sb + 0     + rowA * 64;
    const uint32_t aAl = sb + 8192  + rowA * 64;
    const int rowB = n0w + (lane & 7) + ((lane >> 4) & 1) * 8;
    const int jB   = (lane >> 3) & 1;
    const int swB  = (rowB >> 1) & 3;
    const uint32_t aBh = sb + 16384 + rowB * 64;
    const uint32_t aBl = sb + 24576 + rowB * 64;

    float acc[2][8][4];
#pragma unroll
    for (int mi = 0; mi < 2; mi++)
#pragma unroll
        for (int ni = 0; ni < 8; ni++)
#pragma unroll
            for (int q = 0; q < 4; q++) acc[mi][ni][q] = 0.f;

    float4 pa[4], pb[4];
#pragma unroll
    for (int i = 0; i < 4; i++) { pa[i] = aptr[i]; pb[i] = bptr[i]; }

#pragma unroll 1
    for (int kc = 0; kc < 32; kc++) {
        if (kc) __syncthreads();                 // smem consumed by prev chunk's mma
        {
            uint4 hi, lo;
            split8(pa[0], pa[1], hi, lo);
            *(uint4*)(smbuf + so0)         = hi;
            *(uint4*)(smbuf + 8192 + so0)  = lo;
            split8(pa[2], pa[3], hi, lo);
            *(uint4*)(smbuf + so1)         = hi;
            *(uint4*)(smbuf + 8192 + so1)  = lo;
            split8(pb[0], pb[1], hi, lo);
            *(uint4*)(smbuf + 16384 + so0) = hi;
            *(uint4*)(smbuf + 24576 + so0) = lo;
            split8(pb[2], pb[3], hi, lo);
            *(uint4*)(smbuf + 16384 + so1) = hi;
            *(uint4*)(smbuf + 24576 + so1) = lo;
        }
        __syncthreads();

        if (kc < 31) {                           // prefetch next chunk (hidden by mma)
            const float4* ap = aptr + (kc + 1) * 8;
            const float4* bp = bptr + (kc + 1) * 8;
#pragma unroll
            for (int i = 0; i < 4; i++) { pa[i] = ap[i]; pb[i] = bp[i]; }
        }

#pragma unroll
        for (int kf = 0; kf < 2; kf++) {
            uint32_t Ah[2][4], Al[2][4], Bh[4][4], Bl[4][4];
            const int ja = (((2 * kf + jA) ^ swA) << 4);
            const int jb = (((2 * kf + jB) ^ swB) << 4);
            ldsm4(Ah[0], aAh + ja);
            ldsm4(Ah[1], aAh + 1024 + ja);
            ldsm4(Al[0], aAl + ja);
            ldsm4(Al[1], aAl + 1024 + ja);
#pragma unroll
            for (int ng = 0; ng < 4; ng++) {
                ldsm4(Bh[ng], aBh + ng * 1024 + jb);
                ldsm4(Bl[ng], aBl + ng * 1024 + jb);
            }
            // pass 1: Ahi * Bhi
#pragma unroll
            for (int mi = 0; mi < 2; mi++)
#pragma unroll
                for (int ni = 0; ni < 8; ni++)
                    mma16816(acc[mi][ni], Ah[mi], &Bh[ni >> 1][(ni & 1) * 2]);
            // pass 2: Ahi * Blo
#pragma unroll
            for (int mi = 0; mi < 2; mi++)
#pragma unroll
                for (int ni = 0; ni < 8; ni++)
                    mma16816(acc[mi][ni], Ah[mi], &Bl[ni >> 1][(ni & 1) * 2]);
            // pass 3: Alo * Bhi
#pragma unroll
            for (int mi = 0; mi < 2; mi++)
#pragma unroll
                for (int ni = 0; ni < 8; ni++)
                    mma16816(acc[mi][ni], Al[mi], &Bh[ni >> 1][(ni & 1) * 2]);
        }
    }

    // ---- epilogue: add bias, scatter to out[t][b][n] (m = b*T + t) ----
#pragma unroll
    for (int mi = 0; mi < 2; mi++) {
        int ma = m0 + m0w + mi * 16 + (lane >> 2);
        int mb = ma + 8;
        float* rowa = out + ((size_t)(ma & 127) * Bn + (ma >> 7)) * G4 + n0;
        float* rowb = out + ((size_t)(mb & 127) * Bn + (mb >> 7)) * G4 + n0;
#pragma unroll
        for (int ni = 0; ni < 8; ni++) {
            int nl = n0w + ni * 8 + (lane & 3) * 2;
            float bv0 = bias_s[nl], bv1 = bias_s[nl + 1];
            float2 v;
            v.x = acc[mi][ni][0] + bv0;
            v.y = acc[mi][ni][1] + bv1;
            *(float2*)(rowa + nl) = v;
            v.x = acc[mi][ni][2] + bv0;
            v.y = acc[mi][ni][3] + bv1;
            *(float2*)(rowb + nl) = v;
        }
    }
}

// ============================================================================
// recurrent part (persistent, unchanged from round 3)
// ============================================================================
__device__ __forceinline__ float sigf(float x) { return 1.f / (1.f + expf(-x)); }

__device__ __forceinline__ void grid_barrier() {
    __syncthreads();
    if (threadIdx.x == 0) {
        __threadfence();
        unsigned gen = *(volatile unsigned*)&g_bargen;
        unsigned ticket = atomicAdd(&g_barcnt, 1);
        if (ticket == NCTA - 1) {
            *(volatile unsigned*)&g_barcnt = 0;
            __threadfence();
            atomicAdd(&g_bargen, 1);
        } else {
            while (*(volatile unsigned*)&g_bargen == gen) { __nanosleep(40); }
            __threadfence();
        }
    }
    __syncthreads();
}

#define OFF_W1   0
#define OFF_WI2  8192
#define OFF_WH2  16384
#define OFF_H1S  24576
#define OFF_H2S  28672
#define OFF_G    32768
#define OFF_C1   34880
#define OFF_C2   35392
#define OFF_B2   35904
#define SMEM_F   35968
#define SMEM_BYTES (SMEM_F * 4)

__global__ void __launch_bounds__(256, 1) lstm_persist(
    const float* __restrict__ pre,    // [T][B][512]
    const float* __restrict__ Whh1,   // [512][128]
    const float* __restrict__ Wih2,   // [512][128]
    const float* __restrict__ Whh2,   // [512][128]
    const float* __restrict__ bih2,   // [512]
    const float* __restrict__ bhh2,   // [512]
    float* __restrict__ h2out)        // [B][128]  (d_out)
{
    extern __shared__ float smf[];
    const int tid = threadIdx.x;
    const int bb  = blockIdx.x >> 3;   // batch block 0..15
    const int ub  = blockIdx.x & 7;    // unit block  0..7

    float* W1t  = smf + OFF_W1;
    float* Wi2t = smf + OFF_WI2;
    float* Wh2t = smf + OFF_WH2;
    float* h1s  = smf + OFF_H1S;
    float* h2s  = smf + OFF_H2S;
    float* G    = smf + OFF_G;
    float* c1s  = smf + OFF_C1;
    float* c2s  = smf + OFF_C2;
    float* b2s  = smf + OFF_B2;

    for (int idx = tid; idx < 64 * 128; idx += 256) {
        int j = idx >> 7;
        int k = idx & 127;
        int gcol = ((j >> 4) << 7) + (ub << 4) + (j & 15);
        int so = (k >> 2) * 256 + j * 4 + (k & 3);
        W1t[so]  = Whh1[(size_t)gcol * Hn + k];
        Wi2t[so] = Wih2[(size_t)gcol * Hn + k];
        Wh2t[so] = Whh2[(size_t)gcol * Hn + k];
    }
    if (tid < 64) {
        int gcol = ((tid >> 4) << 7) + (ub << 4) + (tid & 15);
        b2s[tid] = bih2[gcol] + bhh2[gcol];
    }
    for (int i = tid; i < 512; i += 256) { c1s[i] = 0.f; c2s[i] = 0.f; }
    {
        int u = tid & 15;
        int bl = tid >> 4;
#pragma unroll
        for (int i = 0; i < 2; i++) {
            int row = bb * 32 + bl + i * 16;
            int col = ub * 16 + u;
            g_h1[row * Hn + col] = 0.f;
            g_h2[row * Hn + col] = 0.f;
        }
    }
    grid_barrier();

    const int bg = tid >> 6;
    const int j  = tid & 63;
    const int gcol = ((j >> 4) << 7) + (ub << 4) + (j & 15);
    const int u2 = tid & 15;
    const int bl0 = tid >> 4;

    const float4* w1 = (const float4*)W1t;
    const float4* wi2 = (const float4*)Wi2t;
    const float4* wh2 = (const float4*)Wh2t;
    const float4* h1s4 = (const float4*)h1s;
    const float4* h2s4 = (const float4*)h2s;

    for (int t = 0; t < Tn; t++) {
        const int p = t & 1;
        const float* h1cur = g_h1 + p * BH;
        float* h1next      = g_h1 + (1 - p) * BH;
        const float* h2cur = g_h2 + p * BH;
        float* h2next      = g_h2 + (1 - p) * BH;

        // ===== Phase A: layer-1 =====
        {
            const float4* src = (const float4*)(h1cur + (size_t)bb * 32 * Hn);
            float4* dst = (float4*)h1s;
#pragma unroll
            for (int i = 0; i < 4; i++) dst[tid + i * 256] = src[tid + i * 256];
        }
        __syncthreads();

        {
            const float* preb = pre + ((size_t)t * Bn + bb * 32 + bg * 8) * G4 + gcol;
            float acc[8];
#pragma unroll
            for (int b = 0; b < 8; b++) acc[b] = preb[b * G4];
#pragma unroll 8
            for (int k4 = 0; k4 < 32; k4++) {
                float4 wv = w1[k4 * 64 + j];
#pragma unroll
                for (int b = 0; b < 8; b++) {
                    float4 hv = h1s4[(bg * 8 + b) * 32 + k4];
                    acc[b] += wv.x * hv.x + wv.y * hv.y + wv.z * hv.z + wv.w * hv.w;
                }
            }
#pragma unroll
            for (int b = 0; b < 8; b++) G[j * 33 + bg * 8 + b] = acc[b];
        }
        __syncthreads();

#pragma unroll
        for (int i = 0; i < 2; i++) {
            int bl = bl0 + i * 16;
            float iv = G[(0 * 16 + u2) * 33 + bl];
            float fv = G[(1 * 16 + u2) * 33 + bl];
            float gv = G[(2 * 16 + u2) * 33 + bl];
            float ov = G[(3 * 16 + u2) * 33 + bl];
            int ci = bl * 16 + u2;
            float cp = c1s[ci];
            float cn = sigf(fv) * cp + sigf(iv) * tanhf(gv);
            c1s[ci] = cn;
            h1next[(bb * 32 + bl) * Hn + ub * 16 + u2] = sigf(ov) * tanhf(cn);
        }
        __threadfence();
        grid_barrier();

        // ===== Phase B: layer-2 =====
        {
            const float4* s1 = (const float4*)(h1next + (size_t)bb * 32 * Hn);
            const float4* s2 = (const float4*)(h2cur + (size_t)bb * 32 * Hn);
            float4* d1 = (float4*)h1s;
            float4* d2 = (float4*)h2s;
#pragma unroll
            for (int i = 0; i < 4; i++) {
                d1[tid + i * 256] = s1[tid + i * 256];
                d2[tid + i * 256] = s2[tid + i * 256];
            }
        }
        __syncthreads();

        {
            float acc[8];
            float bias = b2s[j];
#pragma unroll
            for (int b = 0; b < 8; b++) acc[b] = bias;
#pragma unroll 8
            for (int k4 = 0; k4 < 32; k4++) {
                float4 wv = wi2[k4 * 64 + j];
#pragma unroll
                for (int b = 0; b < 8; b++) {
                    float4 hv = h1s4[(bg * 8 + b) * 32 + k4];
                    acc[b] += wv.x * hv.x + wv.y * hv.y + wv.z * hv.z + wv.w * hv.w;
                }
            }
#pragma unroll 8
            for (int k4 = 0; k4 < 32; k4++) {
                float4 wv = wh2[k4 * 64 + j];
#pragma unroll
                for (int b = 0; b < 8; b++) {
                    float4 hv = h2s4[(bg * 8 + b) * 32 + k4];
                    acc[b] += wv.x * hv.x + wv.y * hv.y + wv.z * hv.z + wv.w * hv.w;
                }
            }
#pragma unroll
            for (int b = 0; b < 8; b++) G[j * 33 + bg * 8 + b] = acc[b];
        }
        __syncthreads();

        float* h2dst = (t == Tn - 1) ? h2out : h2next;
#pragma unroll
        for (int i = 0; i < 2; i++) {
            int bl = bl0 + i * 16;
            float iv = G[(0 * 16 + u2) * 33 + bl];
            float fv = G[(1 * 16 + u2) * 33 + bl];
            float gv = G[(2 * 16 + u2) * 33 + bl];
            float ov = G[(3 * 16 + u2) * 33 + bl];
            int ci = bl * 16 + u2;
            float cp = c2s[ci];
            float cn = sigf(fv) * cp + sigf(iv) * tanhf(gv);
            c2s[ci] = cn;
            h2dst[(bb * 32 + bl) * Hn + ub * 16 + u2] = sigf(ov) * tanhf(cn);
        }
        __syncthreads();
        if (t < Tn - 1) __threadfence();
    }
}

// -------- launch --------
extern "C" void kernel_launch(void* const* d_in, const int* in_sizes, int n_in,
                              void* d_out, int out_size) {
    const float* feats = (const float*)d_in[0];
    const float* Wih1  = (const float*)d_in[1];
    const float* Whh1  = (const float*)d_in[2];
    const float* bih1  = (const float*)d_in[3];
    const float* bhh1  = (const float*)d_in[4];
    const float* Wih2  = (const float*)d_in[5];
    const float* Whh2  = (const float*)d_in[6];
    const float* bih2  = (const float*)d_in[7];
    const float* bhh2  = (const float*)d_in[8];

    float* pre;
    cudaGetSymbolAddress((void**)&pre, g_pre);

    static int attr_set = 0;
    if (!attr_set) {
        cudaFuncSetAttribute(lstm_persist,
                             cudaFuncAttributeMaxDynamicSharedMemorySize,
                             SMEM_BYTES);
        attr_set = 1;
    }

    // pre[t][b][:] = feats @ Wih1^T + bih1 + bhh1  (split-bf16 mma.sync)
    gemm_pre_mma<<<dim3(4, 512), 256>>>(feats, Wih1, bih1, bhh1, pre);

    lstm_persist<<<NCTA, 256, SMEM_BYTES>>>(
        pre, Whh1, Wih2, Whh2, bih2, bhh2, (float*)d_out);
}

// round 7
// speedup vs baseline: 2.0988x; 1.0039x over previous
#include <cuda_runtime.h>
#include <cuda_fp16.h>
#include <math.h>
#include <stdint.h>

// Problem dims
#define Tn 128
#define Bn 512
#define Dn 1024
#define Hn 128
#define G4 512   // 4*H
#define BH (Bn*Hn)

#define NCTA 128   // persistent grid size

// -------- scratch (device globals: no allocations allowed) --------
__device__ float g_pre[(size_t)Tn * Bn * G4];   // [t][b][4H]
__device__ float g_h1[2 * BH];                  // ping-pong
__device__ float g_h2[2 * BH];                  // ping-pong
__device__ unsigned g_barcnt;                   // zero-init
__device__ unsigned g_bargen;                   // generation counter (monotonic)

// ============================================================================
// helpers
// ============================================================================
__device__ __forceinline__ uint32_t smem_u32(const void* p) {
    uint32_t a;
    asm("{ .reg .u64 t; cvta.to.shared.u64 t, %1; cvt.u32.u64 %0, t; }"
        : "=r"(a) : "l"(p));
    return a;
}

__device__ __forceinline__ void ldsm4(uint32_t* r, uint32_t addr) {
    asm volatile("ldmatrix.sync.aligned.m8n8.x4.shared.b16 {%0,%1,%2,%3}, [%4];"
                 : "=r"(r[0]), "=r"(r[1]), "=r"(r[2]), "=r"(r[3]) : "r"(addr));
}

__device__ __forceinline__ void mma16816h(float* d, const uint32_t* a, const uint32_t* b) {
    asm volatile(
        "mma.sync.aligned.m16n8k16.row.col.f32.f16.f16.f32 "
        "{%0,%1,%2,%3}, {%4,%5,%6,%7}, {%8,%9}, {%0,%1,%2,%3};"
        : "+f"(d[0]), "+f"(d[1]), "+f"(d[2]), "+f"(d[3])
        : "r"(a[0]), "r"(a[1]), "r"(a[2]), "r"(a[3]), "r"(b[0]), "r"(b[1]));
}

// pack 8 consecutive fp32 -> 8 fp16 (one 16B store)
__device__ __forceinline__ uint4 pack8h(float4 v0, float4 v1) {
    __half2 h0 = __floats2half2_rn(v0.x, v0.y);
    __half2 h1 = __floats2half2_rn(v0.z, v0.w);
    __half2 h2 = __floats2half2_rn(v1.x, v1.y);
    __half2 h3 = __floats2half2_rn(v1.z, v1.w);
    return make_uint4(*(uint32_t*)&h0, *(uint32_t*)&h1,
                      *(uint32_t*)&h2, *(uint32_t*)&h3);
}

// ============================================================================
// fp16 mma.sync GEMM (single pass, double-buffered):
// pre[t][b][:] = feats_row(m) @ Wih1^T + bih1 + bhh1
// feats [65536][1024] fp32 (m = b*T + t), Wih1 [512][1024] fp32.
// CTA tile 128x128, K-chunk 32, 8 warps of 32x64. Grid (4 n-tiles, 512 m-tiles).
// Smem per buffer: A fp16 [128][32] @ +0 (8KB), B @ +8192. Two buffers (32KB).
// ============================================================================
__global__ void __launch_bounds__(256, 1) gemm_pre_mma(
    const float* __restrict__ A,     // [65536][1024]
    const float* __restrict__ W,     // [512][1024]
    const float* __restrict__ b1,    // [512]
    const float* __restrict__ b2,    // [512]
    float* __restrict__ out)         // [T][B][512]
{
    __shared__ __align__(128) char smbuf[32768];
    __shared__ float bias_s[128];

    const int tid  = threadIdx.x;
    const int lane = tid & 31;
    const int wid  = tid >> 5;
    const int n0 = blockIdx.x * 128;
    const int m0 = blockIdx.y * 128;
    const uint32_t sb = smem_u32(smbuf);

    if (tid < 128) bias_s[tid] = b1[n0 + tid] + b2[n0 + tid];

    // per-thread store slots: row r (64B rows), two 16B k-units
    const int r   = tid >> 1;
    const int u0  = (tid & 1) * 2;
    const int ssw = (r >> 1) & 3;
    const int so0 = r * 64 + (((u0)     ^ ssw) << 4);
    const int so1 = r * 64 + (((u0 + 1) ^ ssw) << 4);

    const float4* aptr = (const float4*)(A + (size_t)(m0 + r) * Dn) + (tid & 1) * 4;
    const float4* bptr = (const float4*)(W + (size_t)(n0 + r) * Dn) + (tid & 1) * 4;

    // warp tile 32(m) x 64(n)
    const int m0w = (wid >> 1) * 32;
    const int n0w = (wid & 1) * 64;

    const int rowA = m0w + (lane & 15);
    const int jA   = lane >> 4;
    const int swA  = (rowA >> 1) & 3;
    const uint32_t aA = sb + rowA * 64;
    const int rowB = n0w + (lane & 7) + ((lane >> 4) & 1) * 8;
    const int jB   = (lane >> 3) & 1;
    const int swB  = (rowB >> 1) & 3;
    const uint32_t aB = sb + 8192 + rowB * 64;

    float acc[2][8][4];
#pragma unroll
    for (int mi = 0; mi < 2; mi++)
#pragma unroll
        for (int ni = 0; ni < 8; ni++)
#pragma unroll
            for (int q = 0; q < 4; q++) acc[mi][ni][q] = 0.f;

    float4 pa[4], pb[4];
    // prologue: chunk 0 -> buf0
#pragma unroll
    for (int i = 0; i < 4; i++) { pa[i] = aptr[i]; pb[i] = bptr[i]; }
    *(uint4*)(smbuf + so0)        = pack8h(pa[0], pa[1]);
    *(uint4*)(smbuf + so1)        = pack8h(pa[2], pa[3]);
    *(uint4*)(smbuf + 8192 + so0) = pack8h(pb[0], pb[1]);
    *(uint4*)(smbuf + 8192 + so1) = pack8h(pb[2], pb[3]);
    __syncthreads();

#pragma unroll 1
    for (int kc = 0; kc < 32; kc++) {
        const int p = kc & 1;

        if (kc < 31) {  // prefetch next chunk into regs (hidden under mma)
            const float4* ap = aptr + (kc + 1) * 8;
            const float4* bp = bptr + (kc + 1) * 8;
#pragma unroll
            for (int i = 0; i < 4; i++) { pa[i] = ap[i]; pb[i] = bp[i]; }
        }

        const uint32_t ba  = aA + p * 16384;
        const uint32_t bbb = aB + p * 16384;
#pragma unroll
        for (int kf = 0; kf < 2; kf++) {
            uint32_t Af[2][4], Bf[4][4];
            const int ja = (((2 * kf + jA) ^ swA) << 4);
            const int jb = (((2 * kf + jB) ^ swB) << 4);
            ldsm4(Af[0], ba + ja);
            ldsm4(Af[1], ba + 1024 + ja);
#pragma unroll
            for (int ng = 0; ng < 4; ng++)
                ldsm4(Bf[ng], bbb + ng * 1024 + jb);
#pragma unroll
            for (int mi = 0; mi < 2; mi++)
#pragma unroll
                for (int ni = 0; ni < 8; ni++)
                    mma16816h(acc[mi][ni], Af[mi], &Bf[ni >> 1][(ni & 1) * 2]);
        }

        if (kc < 31) {  // store next chunk into the other buffer
            char* d = smbuf + ((p ^ 1) << 14);
            *(uint4*)(d + so0)        = pack8h(pa[0], pa[1]);
            *(uint4*)(d + so1)        = pack8h(pa[2], pa[3]);
            *(uint4*)(d + 8192 + so0) = pack8h(pb[0], pb[1]);
            *(uint4*)(d + 8192 + so1) = pack8h(pb[2], pb[3]);
        }
        __syncthreads();
    }

    // ---- epilogue: add bias, scatter to out[t][b][n] (m = b*T + t) ----
#pragma unroll
    for (int mi = 0; mi < 2; mi++) {
        int ma = m0 + m0w + mi * 16 + (lane >> 2);
        int mb = ma + 8;
        float* rowa = out + ((size_t)(ma & 127) * Bn + (ma >> 7)) * G4 + n0;
        float* rowb = out + ((size_t)(mb & 127) * Bn + (mb >> 7)) * G4 + n0;
#pragma unroll
        for (int ni = 0; ni < 8; ni++) {
            int nl = n0w + ni * 8 + (lane & 3) * 2;
            float bv0 = bias_s[nl], bv1 = bias_s[nl + 1];
            float2 v;
            v.x = acc[mi][ni][0] + bv0;
            v.y = acc[mi][ni][1] + bv1;
            *(float2*)(rowa + nl) = v;
            v.x = acc[mi][ni][2] + bv0;
            v.y = acc[mi][ni][3] + bv1;
            *(float2*)(rowb + nl) = v;
        }
    }
}

// ============================================================================
// recurrent part (persistent, unchanged)
// ============================================================================
__device__ __forceinline__ float sigf(float x) { return 1.f / (1.f + expf(-x)); }

__device__ __forceinline__ void grid_barrier() {
    __syncthreads();
    if (threadIdx.x == 0) {
        __threadfence();
        unsigned gen = *(volatile unsigned*)&g_bargen;
        unsigned ticket = atomicAdd(&g_barcnt, 1);
        if (ticket == NCTA - 1) {
            *(volatile unsigned*)&g_barcnt = 0;
            __threadfence();
            atomicAdd(&g_bargen, 1);
        } else {
            while (*(volatile unsigned*)&g_bargen == gen) { __nanosleep(40); }
            __threadfence();
        }
    }
    __syncthreads();
}

#define OFF_W1   0
#define OFF_WI2  8192
#define OFF_WH2  16384
#define OFF_H1S  24576
#define OFF_H2S  28672
#define OFF_G    32768
#define OFF_C1   34880
#define OFF_C2   35392
#define OFF_B2   35904
#define SMEM_F   35968
#define SMEM_BYTES (SMEM_F * 4)

__global__ void __launch_bounds__(256, 1) lstm_persist(
    const float* __restrict__ pre,    // [T][B][512]
    const float* __restrict__ Whh1,   // [512][128]
    const float* __restrict__ Wih2,   // [512][128]
    const float* __restrict__ Whh2,   // [512][128]
    const float* __restrict__ bih2,   // [512]
    const float* __restrict__ bhh2,   // [512]
    float* __restrict__ h2out)        // [B][128]  (d_out)
{
    extern __shared__ float smf[];
    const int tid = threadIdx.x;
    const int bb  = blockIdx.x >> 3;   // batch block 0..15
    const int ub  = blockIdx.x & 7;    // unit block  0..7

    float* W1t  = smf + OFF_W1;
    float* Wi2t = smf + OFF_WI2;
    float* Wh2t = smf + OFF_WH2;
    float* h1s  = smf + OFF_H1S;
    float* h2s  = smf + OFF_H2S;
    float* G    = smf + OFF_G;
    float* c1s  = smf + OFF_C1;
    float* c2s  = smf + OFF_C2;
    float* b2s  = smf + OFF_B2;

    for (int idx = tid; idx < 64 * 128; idx += 256) {
        int j = idx >> 7;
        int k = idx & 127;
        int gcol = ((j >> 4) << 7) + (ub << 4) + (j & 15);
        int so = (k >> 2) * 256 + j * 4 + (k & 3);
        W1t[so]  = Whh1[(size_t)gcol * Hn + k];
        Wi2t[so] = Wih2[(size_t)gcol * Hn + k];
        Wh2t[so] = Whh2[(size_t)gcol * Hn + k];
    }
    if (tid < 64) {
        int gcol = ((tid >> 4) << 7) + (ub << 4) + (tid & 15);
        b2s[tid] = bih2[gcol] + bhh2[gcol];
    }
    for (int i = tid; i < 512; i += 256) { c1s[i] = 0.f; c2s[i] = 0.f; }
    {
        int u = tid & 15;
        int bl = tid >> 4;
#pragma unroll
        for (int i = 0; i < 2; i++) {
            int row = bb * 32 + bl + i * 16;
            int col = ub * 16 + u;
            g_h1[row * Hn + col] = 0.f;
            g_h2[row * Hn + col] = 0.f;
        }
    }
    grid_barrier();

    const int bg = tid >> 6;
    const int j  = tid & 63;
    const int gcol = ((j >> 4) << 7) + (ub << 4) + (j & 15);
    const int u2 = tid & 15;
    const int bl0 = tid >> 4;

    const float4* w1 = (const float4*)W1t;
    const float4* wi2 = (const float4*)Wi2t;
    const float4* wh2 = (const float4*)Wh2t;
    const float4* h1s4 = (const float4*)h1s;
    const float4* h2s4 = (const float4*)h2s;

    for (int t = 0; t < Tn; t++) {
        const int p = t & 1;
        const float* h1cur = g_h1 + p * BH;
        float* h1next      = g_h1 + (1 - p) * BH;
        const float* h2cur = g_h2 + p * BH;
        float* h2next      = g_h2 + (1 - p) * BH;

        // ===== Phase A: layer-1 =====
        {
            const float4* src = (const float4*)(h1cur + (size_t)bb * 32 * Hn);
            float4* dst = (float4*)h1s;
#pragma unroll
            for (int i = 0; i < 4; i++) dst[tid + i * 256] = src[tid + i * 256];
        }
        __syncthreads();

        {
            const float* preb = pre + ((size_t)t * Bn + bb * 32 + bg * 8) * G4 + gcol;
            float acc[8];
#pragma unroll
            for (int b = 0; b < 8; b++) acc[b] = preb[b * G4];
#pragma unroll 8
            for (int k4 = 0; k4 < 32; k4++) {
                float4 wv = w1[k4 * 64 + j];
#pragma unroll
                for (int b = 0; b < 8; b++) {
                    float4 hv = h1s4[(bg * 8 + b) * 32 + k4];
                    acc[b] += wv.x * hv.x + wv.y * hv.y + wv.z * hv.z + wv.w * hv.w;
                }
            }
#pragma unroll
            for (int b = 0; b < 8; b++) G[j * 33 + bg * 8 + b] = acc[b];
        }
        __syncthreads();

#pragma unroll
        for (int i = 0; i < 2; i++) {
            int bl = bl0 + i * 16;
            float iv = G[(0 * 16 + u2) * 33 + bl];
            float fv = G[(1 * 16 + u2) * 33 + bl];
            float gv = G[(2 * 16 + u2) * 33 + bl];
            float ov = G[(3 * 16 + u2) * 33 + bl];
            int ci = bl * 16 + u2;
            float cp = c1s[ci];
            float cn = sigf(fv) * cp + sigf(iv) * tanhf(gv);
            c1s[ci] = cn;
            h1next[(bb * 32 + bl) * Hn + ub * 16 + u2] = sigf(ov) * tanhf(cn);
        }
        __threadfence();
        grid_barrier();

        // ===== Phase B: layer-2 =====
        {
            const float4* s1 = (const float4*)(h1next + (size_t)bb * 32 * Hn);
            const float4* s2 = (const float4*)(h2cur + (size_t)bb * 32 * Hn);
            float4* d1 = (float4*)h1s;
            float4* d2 = (float4*)h2s;
#pragma unroll
            for (int i = 0; i < 4; i++) {
                d1[tid + i * 256] = s1[tid + i * 256];
                d2[tid + i * 256] = s2[tid + i * 256];
            }
        }
        __syncthreads();

        {
            float acc[8];
            float bias = b2s[j];
#pragma unroll
            for (int b = 0; b < 8; b++) acc[b] = bias;
#pragma unroll 8
            for (int k4 = 0; k4 < 32; k4++) {
                float4 wv = wi2[k4 * 64 + j];
#pragma unroll
                for (int b = 0; b < 8; b++) {
                    float4 hv = h1s4[(bg * 8 + b) * 32 + k4];
                    acc[b] += wv.x * hv.x + wv.y * hv.y + wv.z * hv.z + wv.w * hv.w;
                }
            }
#pragma unroll 8
            for (int k4 = 0; k4 < 32; k4++) {
                float4 wv = wh2[k4 * 64 + j];
#pragma unroll
                for (int b = 0; b < 8; b++) {
                    float4 hv = h2s4[(bg * 8 + b) * 32 + k4];
                    acc[b] += wv.x * hv.x + wv.y * hv.y + wv.z * hv.z + wv.w * hv.w;
                }
            }
#pragma unroll
            for (int b = 0; b < 8; b++) G[j * 33 + bg * 8 + b] = acc[b];
        }
        __syncthreads();

        float* h2dst = (t == Tn - 1) ? h2out : h2next;
#pragma unroll
        for (int i = 0; i < 2; i++) {
            int bl = bl0 + i * 16;
            float iv = G[(0 * 16 + u2) * 33 + bl];
            float fv = G[(1 * 16 + u2) * 33 + bl];
            float gv = G[(2 * 16 + u2) * 33 + bl];
            float ov = G[(3 * 16 + u2) * 33 + bl];
            int ci = bl * 16 + u2;
            float cp = c2s[ci];
            float cn = sigf(fv) * cp + sigf(iv) * tanhf(gv);
            c2s[ci] = cn;
            h2dst[(bb * 32 + bl) * Hn + ub * 16 + u2] = sigf(ov) * tanhf(cn);
        }
        __syncthreads();
        if (t < Tn - 1) __threadfence();
    }
}

// -------- launch --------
extern "C" void kernel_launch(void* const* d_in, const int* in_sizes, int n_in,
                              void* d_out, int out_size) {
    const float* feats = (const float*)d_in[0];
    const float* Wih1  = (const float*)d_in[1];
    const float* Whh1  = (const float*)d_in[2];
    const float* bih1  = (const float*)d_in[3];
    const float* bhh1  = (const float*)d_in[4];
    const float* Wih2  = (const float*)d_in[5];
    const float* Whh2  = (const float*)d_in[6];
    const float* bih2  = (const float*)d_in[7];
    const float* bhh2  = (const float*)d_in[8];

    float* pre;
    cudaGetSymbolAddress((void**)&pre, g_pre);

    static int attr_set = 0;
    if (!attr_set) {
        cudaFuncSetAttribute(lstm_persist,
                             cudaFuncAttributeMaxDynamicSharedMemorySize,
                             SMEM_BYTES);
        attr_set = 1;
    }

    // pre[t][b][:] = feats @ Wih1^T + bih1 + bhh1  (fp16 mma.sync, double-buffered)
    gemm_pre_mma<<<dim3(4, 512), 256>>>(feats, Wih1, bih1, bhh1, pre);

    lstm_persist<<<NCTA, 256, SMEM_BYTES>>>(
        pre, Whh1, Wih2, Whh2, bih2, bhh2, (float*)d_out);
}

// round 8
// speedup vs baseline: 2.4152x; 1.1508x over previous
#include <cuda_runtime.h>
#include <cuda_fp16.h>
#include <math.h>
#include <stdint.h>

// Problem dims
#define Tn 128
#define Bn 512
#define Dn 1024
#define Hn 128
#define G4 512   // 4*H
#define BH (Bn*Hn)

#define NCTA 128   // persistent grid size

// -------- scratch (device globals: no allocations allowed) --------
__device__ float g_pre[(size_t)Tn * Bn * G4];   // [t][b][4H]
__device__ __half g_Ah[(size_t)Bn * Tn * Dn];   // feats in fp16 (134 MB)
__device__ __half g_Wh[G4 * Dn];                // Wih1 in fp16 (1 MB)
__device__ float g_h1[2 * BH];                  // ping-pong
__device__ float g_h2[2 * BH];                  // ping-pong
__device__ unsigned g_barcnt;                   // zero-init
__device__ unsigned g_bargen;                   // generation counter (monotonic)

// ============================================================================
// helpers
// ============================================================================
__device__ __forceinline__ uint32_t smem_u32(const void* p) {
    uint32_t a;
    asm("{ .reg .u64 t; cvta.to.shared.u64 t, %1; cvt.u32.u64 %0, t; }"
        : "=r"(a) : "l"(p));
    return a;
}

__device__ __forceinline__ void ldsm4(uint32_t* r, uint32_t addr) {
    asm volatile("ldmatrix.sync.aligned.m8n8.x4.shared.b16 {%0,%1,%2,%3}, [%4];"
                 : "=r"(r[0]), "=r"(r[1]), "=r"(r[2]), "=r"(r[3]) : "r"(addr));
}

__device__ __forceinline__ void mma16816h(float* d, const uint32_t* a, const uint32_t* b) {
    asm volatile(
        "mma.sync.aligned.m16n8k16.row.col.f32.f16.f16.f32 "
        "{%0,%1,%2,%3}, {%4,%5,%6,%7}, {%8,%9}, {%0,%1,%2,%3};"
        : "+f"(d[0]), "+f"(d[1]), "+f"(d[2]), "+f"(d[3])
        : "r"(a[0]), "r"(a[1]), "r"(a[2]), "r"(a[3]), "r"(b[0]), "r"(b[1]));
}

__device__ __forceinline__ uint4 pack8h(float4 v0, float4 v1) {
    __half2 h0 = __floats2half2_rn(v0.x, v0.y);
    __half2 h1 = __floats2half2_rn(v0.z, v0.w);
    __half2 h2 = __floats2half2_rn(v1.x, v1.y);
    __half2 h3 = __floats2half2_rn(v1.z, v1.w);
    return make_uint4(*(uint32_t*)&h0, *(uint32_t*)&h1,
                      *(uint32_t*)&h2, *(uint32_t*)&h3);
}

#define CP16(dst, src) \
    asm volatile("cp.async.cg.shared.global [%0], [%1], 16;" \
                 :: "r"(dst), "l"(src) : "memory")
#define CP_COMMIT() asm volatile("cp.async.commit_group;" ::: "memory")
#define CP_WAIT1()  asm volatile("cp.async.wait_group 1;" ::: "memory")
#define CP_WAIT0()  asm volatile("cp.async.wait_group 0;" ::: "memory")

// -------- fp32 -> fp16 bulk convert (grid-stride over 8-float groups) --------
__global__ void __launch_bounds__(256) cvt_fp16_kernel(
    const float* __restrict__ s, __half* __restrict__ d, int n8)
{
    int i = blockIdx.x * blockDim.x + threadIdx.x;
    int stride = gridDim.x * blockDim.x;
    for (; i < n8; i += stride) {
        const float4* sp = (const float4*)s + 2 * (size_t)i;
        *(uint4*)((char*)d + 16 * (size_t)i) = pack8h(sp[0], sp[1]);
    }
}

// ============================================================================
// fp16 mma.sync GEMM, cp.async 3-stage pipeline:
// pre[t][b][:] = feats_row(m) @ Wih1^T + bih1 + bhh1
// A fp16 [65536][1024] (m = b*T + t), W fp16 [512][1024].
// CTA tile 128x128, K-chunk 32, 8 warps of 32x64. Grid (4 n-tiles, 512 m-tiles).
// Per stage: A fp16 [128][32] @ +0 (8KB), B @ +8192. 3 stages = 48KB.
// ============================================================================
#define NSTG 3

__global__ void __launch_bounds__(256, 2) gemm_pre_mma(
    const __half* __restrict__ Ah,   // [65536][1024]
    const __half* __restrict__ Wh,   // [512][1024]
    const float* __restrict__ b1,    // [512]
    const float* __restrict__ b2,    // [512]
    float* __restrict__ out)         // [T][B][512]
{
    __shared__ __align__(128) char smbuf[NSTG * 16384];
    __shared__ float bias_s[128];

    const int tid  = threadIdx.x;
    const int lane = tid & 31;
    const int wid  = tid >> 5;
    const int n0 = blockIdx.x * 128;
    const int m0 = blockIdx.y * 128;
    const uint32_t sb = smem_u32(smbuf);

    if (tid < 128) bias_s[tid] = b1[n0 + tid] + b2[n0 + tid];

    // per-thread copy slots: row r (64B rows), two 16B k-units (swizzled dst)
    const int r   = tid >> 1;
    const int u0  = (tid & 1) * 2;
    const int ssw = (r >> 1) & 3;
    const uint32_t so0 = r * 64 + (((u0)     ^ ssw) << 4);
    const uint32_t so1 = r * 64 + (((u0 + 1) ^ ssw) << 4);

    const __half* arow = Ah + (size_t)(m0 + r) * Dn;
    const __half* brow = Wh + (size_t)(n0 + r) * Dn;

    // warp tile 32(m) x 64(n)
    const int m0w = (wid >> 1) * 32;
    const int n0w = (wid & 1) * 64;

    const int rowA = m0w + (lane & 15);
    const int jA   = lane >> 4;
    const int swA  = (rowA >> 1) & 3;
    const uint32_t aA = sb + rowA * 64;
    const int rowB = n0w + (lane & 7) + ((lane >> 4) & 1) * 8;
    const int jB   = (lane >> 3) & 1;
    const int swB  = (rowB >> 1) & 3;
    const uint32_t aB = sb + 8192 + rowB * 64;

    float acc[2][8][4];
#pragma unroll
    for (int mi = 0; mi < 2; mi++)
#pragma unroll
        for (int ni = 0; ni < 8; ni++)
#pragma unroll
            for (int q = 0; q < 4; q++) acc[mi][ni][q] = 0.f;

    // issue chunk kc into stage stg
    auto issue = [&](int kc, int stg) {
        const uint32_t d = sb + stg * 16384;
        const __half* as = arow + kc * 32 + u0 * 8;
        const __half* bs = brow + kc * 32 + u0 * 8;
        CP16(d + so0,        as);
        CP16(d + so1,        as + 8);
        CP16(d + 8192 + so0, bs);
        CP16(d + 8192 + so1, bs + 8);
        CP_COMMIT();
    };

    issue(0, 0);
    issue(1, 1);

#pragma unroll 1
    for (int kc = 0; kc < 32; kc++) {
        if (kc == 31) { CP_WAIT0(); } else { CP_WAIT1(); }
        __syncthreads();

        if (kc < 30) issue(kc + 2, (kc + 2) % NSTG);

        const uint32_t ba  = aA + (kc % NSTG) * 16384;
        const uint32_t bbb = aB + (kc % NSTG) * 16384;
#pragma unroll
        for (int kf = 0; kf < 2; kf++) {
            uint32_t Af[2][4], Bf[4][4];
            const int ja = (((2 * kf + jA) ^ swA) << 4);
            const int jb = (((2 * kf + jB) ^ swB) << 4);
            ldsm4(Af[0], ba + ja);
            ldsm4(Af[1], ba + 1024 + ja);
#pragma unroll
            for (int ng = 0; ng < 4; ng++)
                ldsm4(Bf[ng], bbb + ng * 1024 + jb);
#pragma unroll
            for (int mi = 0; mi < 2; mi++)
#pragma unroll
                for (int ni = 0; ni < 8; ni++)
                    mma16816h(acc[mi][ni], Af[mi], &Bf[ni >> 1][(ni & 1) * 2]);
        }
        __syncthreads();
    }

    // ---- epilogue: add bias, scatter to out[t][b][n] (m = b*T + t) ----
#pragma unroll
    for (int mi = 0; mi < 2; mi++) {
        int ma = m0 + m0w + mi * 16 + (lane >> 2);
        int mb = ma + 8;
        float* rowa = out + ((size_t)(ma & 127) * Bn + (ma >> 7)) * G4 + n0;
        float* rowb = out + ((size_t)(mb & 127) * Bn + (mb >> 7)) * G4 + n0;
#pragma unroll
        for (int ni = 0; ni < 8; ni++) {
            int nl = n0w + ni * 8 + (lane & 3) * 2;
            float bv0 = bias_s[nl], bv1 = bias_s[nl + 1];
            float2 v;
            v.x = acc[mi][ni][0] + bv0;
            v.y = acc[mi][ni][1] + bv1;
            *(float2*)(rowa + nl) = v;
            v.x = acc[mi][ni][2] + bv0;
            v.y = acc[mi][ni][3] + bv1;
            *(float2*)(rowb + nl) = v;
        }
    }
}

// ============================================================================
// recurrent part (persistent, unchanged)
// ============================================================================
__device__ __forceinline__ float sigf(float x) { return 1.f / (1.f + expf(-x)); }

__device__ __forceinline__ void grid_barrier() {
    __syncthreads();
    if (threadIdx.x == 0) {
        __threadfence();
        unsigned gen = *(volatile unsigned*)&g_bargen;
        unsigned ticket = atomicAdd(&g_barcnt, 1);
        if (ticket == NCTA - 1) {
            *(volatile unsigned*)&g_barcnt = 0;
            __threadfence();
            atomicAdd(&g_bargen, 1);
        } else {
            while (*(volatile unsigned*)&g_bargen == gen) { __nanosleep(40); }
            __threadfence();
        }
    }
    __syncthreads();
}

#define OFF_W1   0
#define OFF_WI2  8192
#define OFF_WH2  16384
#define OFF_H1S  24576
#define OFF_H2S  28672
#define OFF_G    32768
#define OFF_C1   34880
#define OFF_C2   35392
#define OFF_B2   35904
#define SMEM_F   35968
#define SMEM_BYTES (SMEM_F * 4)

__global__ void __launch_bounds__(256, 1) lstm_persist(
    const float* __restrict__ pre,    // [T][B][512]
    const float* __restrict__ Whh1,   // [512][128]
    const float* __restrict__ Wih2,   // [512][128]
    const float* __restrict__ Whh2,   // [512][128]
    const float* __restrict__ bih2,   // [512]
    const float* __restrict__ bhh2,   // [512]
    float* __restrict__ h2out)        // [B][128]  (d_out)
{
    extern __shared__ float smf[];
    const int tid = threadIdx.x;
    const int bb  = blockIdx.x >> 3;   // batch block 0..15
    const int ub  = blockIdx.x & 7;    // unit block  0..7

    float* W1t  = smf + OFF_W1;
    float* Wi2t = smf + OFF_WI2;
    float* Wh2t = smf + OFF_WH2;
    float* h1s  = smf + OFF_H1S;
    float* h2s  = smf + OFF_H2S;
    float* G    = smf + OFF_G;
    float* c1s  = smf + OFF_C1;
    float* c2s  = smf + OFF_C2;
    float* b2s  = smf + OFF_B2;

    for (int idx = tid; idx < 64 * 128; idx += 256) {
        int j = idx >> 7;
        int k = idx & 127;
        int gcol = ((j >> 4) << 7) + (ub << 4) + (j & 15);
        int so = (k >> 2) * 256 + j * 4 + (k & 3);
        W1t[so]  = Whh1[(size_t)gcol * Hn + k];
        Wi2t[so] = Wih2[(size_t)gcol * Hn + k];
        Wh2t[so] = Whh2[(size_t)gcol * Hn + k];
    }
    if (tid < 64) {
        int gcol = ((tid >> 4) << 7) + (ub << 4) + (tid & 15);
        b2s[tid] = bih2[gcol] + bhh2[gcol];
    }
    for (int i = tid; i < 512; i += 256) { c1s[i] = 0.f; c2s[i] = 0.f; }
    {
        int u = tid & 15;
        int bl = tid >> 4;
#pragma unroll
        for (int i = 0; i < 2; i++) {
            int row = bb * 32 + bl + i * 16;
            int col = ub * 16 + u;
            g_h1[row * Hn + col] = 0.f;
            g_h2[row * Hn + col] = 0.f;
        }
    }
    grid_barrier();

    const int bg = tid >> 6;
    const int j  = tid & 63;
    const int gcol = ((j >> 4) << 7) + (ub << 4) + (j & 15);
    const int u2 = tid & 15;
    const int bl0 = tid >> 4;

    const float4* w1 = (const float4*)W1t;
    const float4* wi2 = (const float4*)Wi2t;
    const float4* wh2 = (const float4*)Wh2t;
    const float4* h1s4 = (const float4*)h1s;
    const float4* h2s4 = (const float4*)h2s;

    for (int t = 0; t < Tn; t++) {
        const int p = t & 1;
        const float* h1cur = g_h1 + p * BH;
        float* h1next      = g_h1 + (1 - p) * BH;
        const float* h2cur = g_h2 + p * BH;
        float* h2next      = g_h2 + (1 - p) * BH;

        // ===== Phase A: layer-1 =====
        {
            const float4* src = (const float4*)(h1cur + (size_t)bb * 32 * Hn);
            float4* dst = (float4*)h1s;
#pragma unroll
            for (int i = 0; i < 4; i++) dst[tid + i * 256] = src[tid + i * 256];
        }
        __syncthreads();

        {
            const float* preb = pre + ((size_t)t * Bn + bb * 32 + bg * 8) * G4 + gcol;
            float acc[8];
#pragma unroll
            for (int b = 0; b < 8; b++) acc[b] = preb[b * G4];
#pragma unroll 8
            for (int k4 = 0; k4 < 32; k4++) {
                float4 wv = w1[k4 * 64 + j];
#pragma unroll
                for (int b = 0; b < 8; b++) {
                    float4 hv = h1s4[(bg * 8 + b) * 32 + k4];
                    acc[b] += wv.x * hv.x + wv.y * hv.y + wv.z * hv.z + wv.w * hv.w;
                }
            }
#pragma unroll
            for (int b = 0; b < 8; b++) G[j * 33 + bg * 8 + b] = acc[b];
        }
        __syncthreads();

#pragma unroll
        for (int i = 0; i < 2; i++) {
            int bl = bl0 + i * 16;
            float iv = G[(0 * 16 + u2) * 33 + bl];
            float fv = G[(1 * 16 + u2) * 33 + bl];
            float gv = G[(2 * 16 + u2) * 33 + bl];
            float ov = G[(3 * 16 + u2) * 33 + bl];
            int ci = bl * 16 + u2;
            float cp = c1s[ci];
            float cn = sigf(fv) * cp + sigf(iv) * tanhf(gv);
            c1s[ci] = cn;
            h1next[(bb * 32 + bl) * Hn + ub * 16 + u2] = sigf(ov) * tanhf(cn);
        }
        __threadfence();
        grid_barrier();

        // ===== Phase B: layer-2 =====
        {
            const float4* s1 = (const float4*)(h1next + (size_t)bb * 32 * Hn);
            const float4* s2 = (const float4*)(h2cur + (size_t)bb * 32 * Hn);
            float4* d1 = (float4*)h1s;
            float4* d2 = (float4*)h2s;
#pragma unroll
            for (int i = 0; i < 4; i++) {
                d1[tid + i * 256] = s1[tid + i * 256];
                d2[tid + i * 256] = s2[tid + i * 256];
            }
        }
        __syncthreads();

        {
            float acc[8];
            float bias = b2s[j];
#pragma unroll
            for (int b = 0; b < 8; b++) acc[b] = bias;
#pragma unroll 8
            for (int k4 = 0; k4 < 32; k4++) {
                float4 wv = wi2[k4 * 64 + j];
#pragma unroll
                for (int b = 0; b < 8; b++) {
                    float4 hv = h1s4[(bg * 8 + b) * 32 + k4];
                    acc[b] += wv.x * hv.x + wv.y * hv.y + wv.z * hv.z + wv.w * hv.w;
                }
            }
#pragma unroll 8
            for (int k4 = 0; k4 < 32; k4++) {
                float4 wv = wh2[k4 * 64 + j];
#pragma unroll
                for (int b = 0; b < 8; b++) {
                    float4 hv = h2s4[(bg * 8 + b) * 32 + k4];
                    acc[b] += wv.x * hv.x + wv.y * hv.y + wv.z * hv.z + wv.w * hv.w;
                }
            }
#pragma unroll
            for (int b = 0; b < 8; b++) G[j * 33 + bg * 8 + b] = acc[b];
        }
        __syncthreads();

        float* h2dst = (t == Tn - 1) ? h2out : h2next;
#pragma unroll
        for (int i = 0; i < 2; i++) {
            int bl = bl0 + i * 16;
            float iv = G[(0 * 16 + u2) * 33 + bl];
            float fv = G[(1 * 16 + u2) * 33 + bl];
            float gv = G[(2 * 16 + u2) * 33 + bl];
            float ov = G[(3 * 16 + u2) * 33 + bl];
            int ci = bl * 16 + u2;
            float cp = c2s[ci];
            float cn = sigf(fv) * cp + sigf(iv) * tanhf(gv);
            c2s[ci] = cn;
            h2dst[(bb * 32 + bl) * Hn + ub * 16 + u2] = sigf(ov) * tanhf(cn);
        }
        __syncthreads();
        if (t < Tn - 1) __threadfence();
    }
}

// -------- launch --------
extern "C" void kernel_launch(void* const* d_in, const int* in_sizes, int n_in,
                              void* d_out, int out_size) {
    const float* feats = (const float*)d_in[0];
    const float* Wih1  = (const float*)d_in[1];
    const float* Whh1  = (const float*)d_in[2];
    const float* bih1  = (const float*)d_in[3];
    const float* bhh1  = (const float*)d_in[4];
    const float* Wih2  = (const float*)d_in[5];
    const float* Whh2  = (const float*)d_in[6];
    const float* bih2  = (const float*)d_in[7];
    const float* bhh2  = (const float*)d_in[8];

    float* pre;
    __half *Ah, *Wh;
    cudaGetSymbolAddress((void**)&pre, g_pre);
    cudaGetSymbolAddress((void**)&Ah,  g_Ah);
    cudaGetSymbolAddress((void**)&Wh,  g_Wh);

    static int attr_set = 0;
    if (!attr_set) {
        cudaFuncSetAttribute(lstm_persist,
                             cudaFuncAttributeMaxDynamicSharedMemorySize,
                             SMEM_BYTES);
        attr_set = 1;
    }

    // fp32 -> fp16 staging (feats 268MB read / 134MB write; W tiny)
    cvt_fp16_kernel<<<4096, 256>>>(feats, Ah, (Bn * Tn * Dn) / 8);
    cvt_fp16_kernel<<<256, 256>>>(Wih1, Wh, (G4 * Dn) / 8);

    // pre = feats @ Wih1^T + bih1 + bhh1  (fp16 mma.sync, cp.async pipeline)
    gemm_pre_mma<<<dim3(4, 512), 256>>>(Ah, Wh, bih1, bhh1, pre);

    lstm_persist<<<NCTA, 256, SMEM_BYTES>>>(
        pre, Whh1, Wih2, Whh2, bih2, bhh2, (float*)d_out);
}

// round 9
// speedup vs baseline: 5.2489x; 2.1733x over previous
#include <cuda_runtime.h>
#include <cuda_fp16.h>
#include <math.h>
#include <stdint.h>

// Problem dims
#define Tn 128
#define Bn 512
#define Dn 1024
#define Hn 128
#define G4 512   // 4*H
#define BH (Bn*Hn)

#define NCTA 128   // persistent grid size

// -------- scratch (device globals: no allocations allowed) --------
__device__ float  g_pre[(size_t)Tn * Bn * G4];  // [t][b][4H]
__device__ __half g_Ah[(size_t)Bn * Tn * Dn];   // feats fp16
__device__ __half g_Wh[G4 * Dn];                // Wih1 fp16
__device__ __half g_h1h[2 * BH];                // fp16 h1 ping-pong
__device__ __half g_h2h[2 * BH];                // fp16 h2 ping-pong
__device__ unsigned g_barcnt;
__device__ unsigned g_bargen;

// ============================================================================
// helpers
// ============================================================================
__device__ __forceinline__ uint32_t smem_u32(const void* p) {
    uint32_t a;
    asm("{ .reg .u64 t; cvta.to.shared.u64 t, %1; cvt.u32.u64 %0, t; }"
        : "=r"(a) : "l"(p));
    return a;
}

__device__ __forceinline__ void ldsm4(uint32_t* r, uint32_t addr) {
    asm volatile("ldmatrix.sync.aligned.m8n8.x4.shared.b16 {%0,%1,%2,%3}, [%4];"
                 : "=r"(r[0]), "=r"(r[1]), "=r"(r[2]), "=r"(r[3]) : "r"(addr));
}

__device__ __forceinline__ void mma16816h(float* d, const uint32_t* a, const uint32_t* b) {
    asm volatile(
        "mma.sync.aligned.m16n8k16.row.col.f32.f16.f16.f32 "
        "{%0,%1,%2,%3}, {%4,%5,%6,%7}, {%8,%9}, {%0,%1,%2,%3};"
        : "+f"(d[0]), "+f"(d[1]), "+f"(d[2]), "+f"(d[3])
        : "r"(a[0]), "r"(a[1]), "r"(a[2]), "r"(a[3]), "r"(b[0]), "r"(b[1]));
}

__device__ __forceinline__ uint4 pack8h(float4 v0, float4 v1) {
    __half2 h0 = __floats2half2_rn(v0.x, v0.y);
    __half2 h1 = __floats2half2_rn(v0.z, v0.w);
    __half2 h2 = __floats2half2_rn(v1.x, v1.y);
    __half2 h3 = __floats2half2_rn(v1.z, v1.w);
    return make_uint4(*(uint32_t*)&h0, *(uint32_t*)&h1,
                      *(uint32_t*)&h2, *(uint32_t*)&h3);
}

#define CP16(dst, src) \
    asm volatile("cp.async.cg.shared.global [%0], [%1], 16;" \
                 :: "r"(dst), "l"(src) : "memory")
#define CP_COMMIT() asm volatile("cp.async.commit_group;" ::: "memory")
#define CP_WAIT1()  asm volatile("cp.async.wait_group 1;" ::: "memory")
#define CP_WAIT0()  asm volatile("cp.async.wait_group 0;" ::: "memory")

// -------- fp32 -> fp16 bulk convert --------
__global__ void __launch_bounds__(256) cvt_fp16_kernel(
    const float* __restrict__ s, __half* __restrict__ d, int n8)
{
    int i = blockIdx.x * blockDim.x + threadIdx.x;
    int stride = gridDim.x * blockDim.x;
    for (; i < n8; i += stride) {
        const float4* sp = (const float4*)s + 2 * (size_t)i;
        *(uint4*)((char*)d + 16 * (size_t)i) = pack8h(sp[0], sp[1]);
    }
}

// ============================================================================
// pre-projection GEMM (unchanged from round 8)
// ============================================================================
#define NSTG 3

__global__ void __launch_bounds__(256, 2) gemm_pre_mma(
    const __half* __restrict__ Ah,   // [65536][1024]
    const __half* __restrict__ Wh,   // [512][1024]
    const float* __restrict__ b1,    // [512]
    const float* __restrict__ b2,    // [512]
    float* __restrict__ out)         // [T][B][512]
{
    __shared__ __align__(128) char smbuf[NSTG * 16384];
    __shared__ float bias_s[128];

    const int tid  = threadIdx.x;
    const int lane = tid & 31;
    const int wid  = tid >> 5;
    const int n0 = blockIdx.x * 128;
    const int m0 = blockIdx.y * 128;
    const uint32_t sb = smem_u32(smbuf);

    if (tid < 128) bias_s[tid] = b1[n0 + tid] + b2[n0 + tid];

    const int r   = tid >> 1;
    const int u0  = (tid & 1) * 2;
    const int ssw = (r >> 1) & 3;
    const uint32_t so0 = r * 64 + (((u0)     ^ ssw) << 4);
    const uint32_t so1 = r * 64 + (((u0 + 1) ^ ssw) << 4);

    const __half* arow = Ah + (size_t)(m0 + r) * Dn;
    const __half* brow = Wh + (size_t)(n0 + r) * Dn;

    const int m0w = (wid >> 1) * 32;
    const int n0w = (wid & 1) * 64;

    const int rowA = m0w + (lane & 15);
    const int jA   = lane >> 4;
    const int swA  = (rowA >> 1) & 3;
    const uint32_t aA = sb + rowA * 64;
    const int rowB = n0w + (lane & 7) + ((lane >> 4) & 1) * 8;
    const int jB   = (lane >> 3) & 1;
    const int swB  = (rowB >> 1) & 3;
    const uint32_t aB = sb + 8192 + rowB * 64;

    float acc[2][8][4];
#pragma unroll
    for (int mi = 0; mi < 2; mi++)
#pragma unroll
        for (int ni = 0; ni < 8; ni++)
#pragma unroll
            for (int q = 0; q < 4; q++) acc[mi][ni][q] = 0.f;

    auto issue = [&](int kc, int stg) {
        const uint32_t d = sb + stg * 16384;
        const __half* as = arow + kc * 32 + u0 * 8;
        const __half* bs = brow + kc * 32 + u0 * 8;
        CP16(d + so0,        as);
        CP16(d + so1,        as + 8);
        CP16(d + 8192 + so0, bs);
        CP16(d + 8192 + so1, bs + 8);
        CP_COMMIT();
    };

    issue(0, 0);
    issue(1, 1);

#pragma unroll 1
    for (int kc = 0; kc < 32; kc++) {
        if (kc == 31) { CP_WAIT0(); } else { CP_WAIT1(); }
        __syncthreads();

        if (kc < 30) issue(kc + 2, (kc + 2) % NSTG);

        const uint32_t ba  = aA + (kc % NSTG) * 16384;
        const uint32_t bbb = aB + (kc % NSTG) * 16384;
#pragma unroll
        for (int kf = 0; kf < 2; kf++) {
            uint32_t Af[2][4], Bf[4][4];
            const int ja = (((2 * kf + jA) ^ swA) << 4);
            const int jb = (((2 * kf + jB) ^ swB) << 4);
            ldsm4(Af[0], ba + ja);
            ldsm4(Af[1], ba + 1024 + ja);
#pragma unroll
            for (int ng = 0; ng < 4; ng++)
                ldsm4(Bf[ng], bbb + ng * 1024 + jb);
#pragma unroll
            for (int mi = 0; mi < 2; mi++)
#pragma unroll
                for (int ni = 0; ni < 8; ni++)
                    mma16816h(acc[mi][ni], Af[mi], &Bf[ni >> 1][(ni & 1) * 2]);
        }
        __syncthreads();
    }

#pragma unroll
    for (int mi = 0; mi < 2; mi++) {
        int ma = m0 + m0w + mi * 16 + (lane >> 2);
        int mb = ma + 8;
        float* rowa = out + ((size_t)(ma & 127) * Bn + (ma >> 7)) * G4 + n0;
        float* rowb = out + ((size_t)(mb & 127) * Bn + (mb >> 7)) * G4 + n0;
#pragma unroll
        for (int ni = 0; ni < 8; ni++) {
            int nl = n0w + ni * 8 + (lane & 3) * 2;
            float bv0 = bias_s[nl], bv1 = bias_s[nl + 1];
            float2 v;
            v.x = acc[mi][ni][0] + bv0;
            v.y = acc[mi][ni][1] + bv1;
            *(float2*)(rowa + nl) = v;
            v.x = acc[mi][ni][2] + bv0;
            v.y = acc[mi][ni][3] + bv1;
            *(float2*)(rowb + nl) = v;
        }
    }
}

// ============================================================================
// persistent recurrence, HMMA version
// Grid: 128 CTAs = 16 batch-blocks (32 rows) x 8 unit-blocks (16 units).
// Local gate-column j (0..63) <-> global gcol = (j>>4)*128 + ub*16 + (j&15).
// ============================================================================
__device__ __forceinline__ float sigf(float x) { return 1.f / (1.f + expf(-x)); }

__device__ __forceinline__ void grid_barrier() {
    __syncthreads();
    if (threadIdx.x == 0) {
        unsigned gen = *(volatile unsigned*)&g_bargen;
        unsigned ticket = atomicAdd(&g_barcnt, 1);
        if (ticket == NCTA - 1) {
            *(volatile unsigned*)&g_barcnt = 0;
            __threadfence();
            atomicAdd(&g_bargen, 1);
        } else {
            while (*(volatile unsigned*)&g_bargen == gen) { __nanosleep(40); }
            __threadfence();
        }
    }
    __syncthreads();
}

// SMEM byte offsets
#define ROF_W1   0          // Whh1 fp16 [64][128] swizzled, 16KB
#define ROF_WI2  16384
#define ROF_WH2  32768
#define ROF_HA   49152      // h tile A: [32][128] fp16 swizzled, 8KB
#define ROF_HB   57344      // h tile B
#define ROF_G    65536      // gates fp32 [32][68]  (8704 B)
#define ROF_PRE  74240      // pre slice fp32 [2][32][64] (16384 B)
#define ROF_C1   90624      // c1 fp32 [512] (2KB)
#define ROF_C2   92672
#define ROF_B2   94720      // bias2 fp32 [64]
#define R_SMEM   95040

#define GS 68   // G row stride (floats)

__global__ void __launch_bounds__(256, 1) lstm_persist(
    const float* __restrict__ pre,    // [T][B][512]
    const float* __restrict__ Whh1,   // [512][128]
    const float* __restrict__ Wih2,   // [512][128]
    const float* __restrict__ Whh2,   // [512][128]
    const float* __restrict__ bih2,   // [512]
    const float* __restrict__ bhh2,   // [512]
    float* __restrict__ h2out)        // [B][128] (d_out)
{
    extern __shared__ char sm[];
    const uint32_t sb = smem_u32(sm);
    const int tid  = threadIdx.x;
    const int lane = tid & 31;
    const int wid  = tid >> 5;
    const int bb   = blockIdx.x >> 3;   // 0..15
    const int ub   = blockIdx.x & 7;    // 0..7

    float* Gf  = (float*)(sm + ROF_G);
    float* prs = (float*)(sm + ROF_PRE);
    float* c1s = (float*)(sm + ROF_C1);
    float* c2s = (float*)(sm + ROF_C2);
    float* b2s = (float*)(sm + ROF_B2);

    // ---- init: weights -> fp16 smem (swizzled), zero state ----
    for (int idx = tid; idx < 64 * 128; idx += 256) {
        int j = idx >> 7;
        int k = idx & 127;
        int gcol = ((j >> 4) << 7) + (ub << 4) + (j & 15);
        uint32_t ad = (uint32_t)(j * 256 + (((k >> 3) ^ (j & 7)) << 4) + (k & 7) * 2);
        *(__half*)(sm + ROF_W1  + ad) = __float2half(Whh1[(size_t)gcol * Hn + k]);
        *(__half*)(sm + ROF_WI2 + ad) = __float2half(Wih2[(size_t)gcol * Hn + k]);
        *(__half*)(sm + ROF_WH2 + ad) = __float2half(Whh2[(size_t)gcol * Hn + k]);
    }
    if (tid < 64) {
        int gcol = ((tid >> 4) << 7) + (ub << 4) + (tid & 15);
        b2s[tid] = bih2[gcol] + bhh2[gcol];
    }
    for (int i = tid; i < 512; i += 256) { c1s[i] = 0.f; c2s[i] = 0.f; }
    // zero hA smem tile (h1 at t=0 is zero) and our slices of h1[0], h2[0]
    for (int i = tid; i < 2048; i += 256) ((uint32_t*)(sm + ROF_HA))[i] = 0;
    {
        int u = tid & 15;
        int bl = tid >> 4;
#pragma unroll
        for (int i = 0; i < 2; i++) {
            int row = bb * 32 + bl + i * 16;
            g_h1h[row * Hn + ub * 16 + u] = __float2half(0.f);
            g_h2h[row * Hn + ub * 16 + u] = __float2half(0.f);
        }
    }
    // prefetch pre[0] slice into pres buf 0
    {
#pragma unroll
        for (int i = 0; i < 2; i++) {
            int q = 2 * tid + i;          // 0..511
            int b = q >> 4, ch = q & 15;
            int gcol0 = ((ch >> 2) << 7) + (ub << 4) + (ch & 3) * 4;
            const float* src = pre + ((size_t)(bb * 32 + b)) * G4 + gcol0;
            CP16(sb + ROF_PRE + (b * 64 + ch * 4) * 4, src);
        }
        CP_COMMIT();
    }
    __threadfence();
    grid_barrier();

    // ---- per-thread mma geometry (warp tile 16m x 16n; 2x4 warp grid) ----
    const int m_off = (wid >> 2) * 16;
    const int n_off = (wid & 3) * 16;
    const int rowA = m_off + (lane & 15);
    const uint32_t aoffA = rowA * 256;
    const int swA = rowA & 7;
    const int kuA0 = lane >> 4;
    const int rowB = n_off + (lane & 7) + ((lane >> 4) & 1) * 8;
    const uint32_t boffB = rowB * 256;
    const int swB = rowB & 7;
    const int kuB0 = (lane >> 3) & 1;

    const int u2  = tid & 15;
    const int bq  = (tid >> 4) * 2;   // base batch row (handles bq, bq+1)

    // GEMM over one K=128 h-tile, accumulate
    auto gemm_acc = [&](uint32_t hbase, uint32_t wbase, float acc[2][4]) {
#pragma unroll
        for (int ks = 0; ks < 8; ks++) {
            uint32_t Af[4], Bf[4];
            int kuA = 2 * ks + kuA0;
            int kuB = 2 * ks + kuB0;
            ldsm4(Af, sb + hbase + aoffA + (uint32_t)(((kuA ^ swA)) << 4));
            ldsm4(Bf, sb + wbase + boffB + (uint32_t)(((kuB ^ swB)) << 4));
            mma16816h(acc[0], Af, Bf);
            mma16816h(acc[1], Af, Bf + 2);
        }
    };
    auto stage_G = [&](float acc[2][4]) {
        int r0 = m_off + (lane >> 2);
        int c0 = n_off + 2 * (lane & 3);
#pragma unroll
        for (int h = 0; h < 2; h++) {   // n8 halves
            Gf[r0 * GS + c0 + 8 * h]           = acc[h][0];
            Gf[r0 * GS + c0 + 8 * h + 1]       = acc[h][1];
            Gf[(r0 + 8) * GS + c0 + 8 * h]     = acc[h][2];
            Gf[(r0 + 8) * GS + c0 + 8 * h + 1] = acc[h][3];
        }
    };

#pragma unroll 1
    for (int t = 0; t < Tn; t++) {
        const int p = t & 1;
        const __half* h2cur = g_h2h + p * BH;
        __half* h1nxt = g_h1h + (1 - p) * BH;
        __half* h2nxt = g_h2h + (1 - p) * BH;
        float* presc = prs + p * 2048;        // pre slice for this step

        // ===== Phase A: layer-1 gates = hA @ W1^T  (+ pre) =====
        // hA already holds h1cur tile (loaded by phase B of t-1; zeros at t=0)
        CP_WAIT0();
        __syncthreads();
        {
            float acc[2][4];
#pragma unroll
            for (int q = 0; q < 2; q++)
#pragma unroll
                for (int w = 0; w < 4; w++) acc[q][w] = 0.f;
            gemm_acc(ROF_HA, ROF_W1, acc);
            stage_G(acc);
        }
        __syncthreads();
#pragma unroll
        for (int i = 0; i < 2; i++) {
            int b = bq + i;
            float iv = Gf[b * GS + u2]      + presc[b * 64 + u2];
            float fv = Gf[b * GS + 16 + u2] + presc[b * 64 + 16 + u2];
            float gv = Gf[b * GS + 32 + u2] + presc[b * 64 + 32 + u2];
            float ov = Gf[b * GS + 48 + u2] + presc[b * 64 + 48 + u2];
            int ci = b * 16 + u2;
            float cp = c1s[ci];
            float cn = sigf(fv) * cp + sigf(iv) * tanhf(gv);
            c1s[ci] = cn;
            h1nxt[(bb * 32 + b) * Hn + ub * 16 + u2] = __float2half(sigf(ov) * tanhf(cn));
        }
        __threadfence();
        grid_barrier();

        // ===== Phase B: layer-2 gates = h1new @ Wi2^T + h2 @ Wh2^T + b2 =====
        // load hA <- h1nxt tile, hB <- h2cur tile (group 1)
        {
#pragma unroll
            for (int i = 0; i < 2; i++) {
                int q = 2 * tid + i;
                int rr = q >> 4, ku = q & 15;
                uint32_t doff = (uint32_t)(rr * 256 + ((ku ^ (rr & 7)) << 4));
                CP16(sb + ROF_HA + doff, h1nxt + (bb * 32 + rr) * Hn + ku * 8);
                CP16(sb + ROF_HB + doff, h2cur + (bb * 32 + rr) * Hn + ku * 8);
            }
            CP_COMMIT();
        }
        // prefetch pre[t+1] (group 2, stays in flight through phase B)
        if (t < Tn - 1) {
#pragma unroll
            for (int i = 0; i < 2; i++) {
                int q = 2 * tid + i;
                int b = q >> 4, ch = q & 15;
                int gcol0 = ((ch >> 2) << 7) + (ub << 4) + (ch & 3) * 4;
                const float* src = pre + ((size_t)(t + 1) * Bn + bb * 32 + b) * G4 + gcol0;
                CP16(sb + ROF_PRE + ((1 - p) * 2048 + b * 64 + ch * 4) * 4, src);
            }
            CP_COMMIT();
            CP_WAIT1();
        } else {
            CP_WAIT0();
        }
        __syncthreads();
        {
            float acc[2][4];
#pragma unroll
            for (int q = 0; q < 2; q++)
#pragma unroll
                for (int w = 0; w < 4; w++) acc[q][w] = 0.f;
            gemm_acc(ROF_HA, ROF_WI2, acc);
            gemm_acc(ROF_HB, ROF_WH2, acc);
            stage_G(acc);
        }
        __syncthreads();
#pragma unroll
        for (int i = 0; i < 2; i++) {
            int b = bq + i;
            float iv = Gf[b * GS + u2]      + b2s[u2];
            float fv = Gf[b * GS + 16 + u2] + b2s[16 + u2];
            float gv = Gf[b * GS + 32 + u2] + b2s[32 + u2];
            float ov = Gf[b * GS + 48 + u2] + b2s[48 + u2];
            int ci = b * 16 + u2;
            float cp = c2s[ci];
            float cn = sigf(fv) * cp + sigf(iv) * tanhf(gv);
            c2s[ci] = cn;
            float hn = sigf(ov) * tanhf(cn);
            h2nxt[(bb * 32 + b) * Hn + ub * 16 + u2] = __float2half(hn);
            if (t == Tn - 1)
                h2out[(bb * 32 + b) * Hn + ub * 16 + u2] = hn;
        }
        __syncthreads();
    }
}

// -------- launch --------
extern "C" void kernel_launch(void* const* d_in, const int* in_sizes, int n_in,
                              void* d_out, int out_size) {
    const float* feats = (const float*)d_in[0];
    const float* Wih1  = (const float*)d_in[1];
    const float* Whh1  = (const float*)d_in[2];
    const float* bih1  = (const float*)d_in[3];
    const float* bhh1  = (const float*)d_in[4];
    const float* Wih2  = (const float*)d_in[5];
    const float* Whh2  = (const float*)d_in[6];
    const float* bih2  = (const float*)d_in[7];
    const float* bhh2  = (const float*)d_in[8];

    float* pre;
    __half *Ah, *Wh;
    cudaGetSymbolAddress((void**)&pre, g_pre);
    cudaGetSymbolAddress((void**)&Ah,  g_Ah);
    cudaGetSymbolAddress((void**)&Wh,  g_Wh);

    static int attr_set = 0;
    if (!attr_set) {
        cudaFuncSetAttribute(lstm_persist,
                             cudaFuncAttributeMaxDynamicSharedMemorySize,
                             R_SMEM);
        attr_set = 1;
    }

    // fp32 -> fp16 staging
    cvt_fp16_kernel<<<4096, 256>>>(feats, Ah, (Bn * Tn * Dn) / 8);
    cvt_fp16_kernel<<<256, 256>>>(Wih1, Wh, (G4 * Dn) / 8);

    // pre = feats @ Wih1^T + bih1 + bhh1
    gemm_pre_mma<<<dim3(4, 512), 256>>>(Ah, Wh, bih1, bhh1, pre);

    lstm_persist<<<NCTA, 256, R_SMEM>>>(
        pre, Whh1, Wih2, Whh2, bih2, bhh2, (float*)d_out);
}

// round 10
// speedup vs baseline: 5.8858x; 1.1213x over previous
#include <cuda_runtime.h>
#include <cuda_fp16.h>
#include <math.h>
#include <stdint.h>

// Problem dims
#define Tn 128
#define Bn 512
#define Dn 1024
#define Hn 128
#define G4 512   // 4*H
#define BH (Bn*Hn)

// -------- scratch (device globals: no allocations allowed) --------
__device__ float  g_pre[(size_t)Tn * Bn * G4];  // [t][b][4H]
__device__ __half g_Ah[(size_t)Bn * Tn * Dn];   // feats fp16
__device__ __half g_Wh[G4 * Dn];                // Wih1 fp16
__device__ __half g_h1h[2 * BH];                // fp16 h1 ping-pong
__device__ __half g_h2h[2 * BH];                // fp16 h2 ping-pong
__device__ unsigned g_gcnt[16 * 32];            // per-group barrier counters (128B apart)
__device__ unsigned g_ggen[16 * 32];            // per-group generations

// ============================================================================
// helpers
// ============================================================================
__device__ __forceinline__ uint32_t smem_u32(const void* p) {
    uint32_t a;
    asm("{ .reg .u64 t; cvta.to.shared.u64 t, %1; cvt.u32.u64 %0, t; }"
        : "=r"(a) : "l"(p));
    return a;
}

__device__ __forceinline__ void ldsm4(uint32_t* r, uint32_t addr) {
    asm volatile("ldmatrix.sync.aligned.m8n8.x4.shared.b16 {%0,%1,%2,%3}, [%4];"
                 : "=r"(r[0]), "=r"(r[1]), "=r"(r[2]), "=r"(r[3]) : "r"(addr));
}

__device__ __forceinline__ void mma16816h(float* d, const uint32_t* a, const uint32_t* b) {
    asm volatile(
        "mma.sync.aligned.m16n8k16.row.col.f32.f16.f16.f32 "
        "{%0,%1,%2,%3}, {%4,%5,%6,%7}, {%8,%9}, {%0,%1,%2,%3};"
        : "+f"(d[0]), "+f"(d[1]), "+f"(d[2]), "+f"(d[3])
        : "r"(a[0]), "r"(a[1]), "r"(a[2]), "r"(a[3]), "r"(b[0]), "r"(b[1]));
}

__device__ __forceinline__ uint4 pack8h(float4 v0, float4 v1) {
    __half2 h0 = __floats2half2_rn(v0.x, v0.y);
    __half2 h1 = __floats2half2_rn(v0.z, v0.w);
    __half2 h2 = __floats2half2_rn(v1.x, v1.y);
    __half2 h3 = __floats2half2_rn(v1.z, v1.w);
    return make_uint4(*(uint32_t*)&h0, *(uint32_t*)&h1,
                      *(uint32_t*)&h2, *(uint32_t*)&h3);
}

#define CP16(dst, src) \
    asm volatile("cp.async.cg.shared.global [%0], [%1], 16;" \
                 :: "r"(dst), "l"(src) : "memory")
#define CP_COMMIT() asm volatile("cp.async.commit_group;" ::: "memory")
#define CP_WAIT1()  asm volatile("cp.async.wait_group 1;" ::: "memory")
#define CP_WAIT0()  asm volatile("cp.async.wait_group 0;" ::: "memory")

// -------- fp32 -> fp16 bulk convert --------
__global__ void __launch_bounds__(256) cvt_fp16_kernel(
    const float* __restrict__ s, __half* __restrict__ d, int n8)
{
    int i = blockIdx.x * blockDim.x + threadIdx.x;
    int stride = gridDim.x * blockDim.x;
    for (; i < n8; i += stride) {
        const float4* sp = (const float4*)s + 2 * (size_t)i;
        *(uint4*)((char*)d + 16 * (size_t)i) = pack8h(sp[0], sp[1]);
    }
}

// ============================================================================
// pre-projection GEMM (unchanged, validated)
// ============================================================================
#define NSTG 3

__global__ void __launch_bounds__(256, 2) gemm_pre_mma(
    const __half* __restrict__ Ah,   // [65536][1024]
    const __half* __restrict__ Wh,   // [512][1024]
    const float* __restrict__ b1,    // [512]
    const float* __restrict__ b2,    // [512]
    float* __restrict__ out)         // [T][B][512]
{
    __shared__ __align__(128) char smbuf[NSTG * 16384];
    __shared__ float bias_s[128];

    const int tid  = threadIdx.x;
    const int lane = tid & 31;
    const int wid  = tid >> 5;
    const int n0 = blockIdx.x * 128;
    const int m0 = blockIdx.y * 128;
    const uint32_t sb = smem_u32(smbuf);

    if (tid < 128) bias_s[tid] = b1[n0 + tid] + b2[n0 + tid];

    const int r   = tid >> 1;
    const int u0  = (tid & 1) * 2;
    const int ssw = (r >> 1) & 3;
    const uint32_t so0 = r * 64 + (((u0)     ^ ssw) << 4);
    const uint32_t so1 = r * 64 + (((u0 + 1) ^ ssw) << 4);

    const __half* arow = Ah + (size_t)(m0 + r) * Dn;
    const __half* brow = Wh + (size_t)(n0 + r) * Dn;

    const int m0w = (wid >> 1) * 32;
    const int n0w = (wid & 1) * 64;

    const int rowA = m0w + (lane & 15);
    const int jA   = lane >> 4;
    const int swA  = (rowA >> 1) & 3;
    const uint32_t aA = sb + rowA * 64;
    const int rowB = n0w + (lane & 7) + ((lane >> 4) & 1) * 8;
    const int jB   = (lane >> 3) & 1;
    const int swB  = (rowB >> 1) & 3;
    const uint32_t aB = sb + 8192 + rowB * 64;

    float acc[2][8][4];
#pragma unroll
    for (int mi = 0; mi < 2; mi++)
#pragma unroll
        for (int ni = 0; ni < 8; ni++)
#pragma unroll
            for (int q = 0; q < 4; q++) acc[mi][ni][q] = 0.f;

    auto issue = [&](int kc, int stg) {
        const uint32_t d = sb + stg * 16384;
        const __half* as = arow + kc * 32 + u0 * 8;
        const __half* bs = brow + kc * 32 + u0 * 8;
        CP16(d + so0,        as);
        CP16(d + so1,        as + 8);
        CP16(d + 8192 + so0, bs);
        CP16(d + 8192 + so1, bs + 8);
        CP_COMMIT();
    };

    issue(0, 0);
    issue(1, 1);

#pragma unroll 1
    for (int kc = 0; kc < 32; kc++) {
        if (kc == 31) { CP_WAIT0(); } else { CP_WAIT1(); }
        __syncthreads();

        if (kc < 30) issue(kc + 2, (kc + 2) % NSTG);

        const uint32_t ba  = aA + (kc % NSTG) * 16384;
        const uint32_t bbb = aB + (kc % NSTG) * 16384;
#pragma unroll
        for (int kf = 0; kf < 2; kf++) {
            uint32_t Af[2][4], Bf[4][4];
            const int ja = (((2 * kf + jA) ^ swA) << 4);
            const int jb = (((2 * kf + jB) ^ swB) << 4);
            ldsm4(Af[0], ba + ja);
            ldsm4(Af[1], ba + 1024 + ja);
#pragma unroll
            for (int ng = 0; ng < 4; ng++)
                ldsm4(Bf[ng], bbb + ng * 1024 + jb);
#pragma unroll
            for (int mi = 0; mi < 2; mi++)
#pragma unroll
                for (int ni = 0; ni < 8; ni++)
                    mma16816h(acc[mi][ni], Af[mi], &Bf[ni >> 1][(ni & 1) * 2]);
        }
        __syncthreads();
    }

#pragma unroll
    for (int mi = 0; mi < 2; mi++) {
        int ma = m0 + m0w + mi * 16 + (lane >> 2);
        int mb = ma + 8;
        float* rowa = out + ((size_t)(ma & 127) * Bn + (ma >> 7)) * G4 + n0;
        float* rowb = out + ((size_t)(mb & 127) * Bn + (mb >> 7)) * G4 + n0;
#pragma unroll
        for (int ni = 0; ni < 8; ni++) {
            int nl = n0w + ni * 8 + (lane & 3) * 2;
            float bv0 = bias_s[nl], bv1 = bias_s[nl + 1];
            float2 v;
            v.x = acc[mi][ni][0] + bv0;
            v.y = acc[mi][ni][1] + bv1;
            *(float2*)(rowa + nl) = v;
            v.x = acc[mi][ni][2] + bv0;
            v.y = acc[mi][ni][3] + bv1;
            *(float2*)(rowb + nl) = v;
        }
    }
}

// ============================================================================
// persistent recurrence, HMMA + per-group (8-CTA) barriers
// Grid: 128 CTAs = 16 batch-blocks x 8 unit-blocks; all cross-CTA deps are
// within one batch-block group, so sync only those 8 CTAs.
// ============================================================================
__device__ __forceinline__ float sigf(float x) {
    return __fdividef(1.f, 1.f + __expf(-x));
}
__device__ __forceinline__ float tanhfast(float x) {
    return __fmaf_rn(2.f, __fdividef(1.f, 1.f + __expf(-2.f * x)), -1.f);
}

// CG-style: syncthreads (CTA-scope ordering) + single release fence by the
// arriving thread; cumulativity makes all CTA threads' prior stores visible.
__device__ __forceinline__ void group_barrier(int grp) {
    __syncthreads();
    if (threadIdx.x == 0) {
        const int s = grp * 32;
        __threadfence();
        unsigned gen = *(volatile unsigned*)&g_ggen[s];
        unsigned ticket = atomicAdd(&g_gcnt[s], 1);
        if (ticket == 7) {
            *(volatile unsigned*)&g_gcnt[s] = 0;
            __threadfence();
            atomicAdd(&g_ggen[s], 1);
        } else {
            while (*(volatile unsigned*)&g_ggen[s] == gen) { __nanosleep(20); }
            __threadfence();
        }
    }
    __syncthreads();
}

// SMEM byte offsets
#define ROF_W1   0          // Whh1 fp16 [64][128] swizzled, 16KB
#define ROF_WI2  16384
#define ROF_WH2  32768
#define ROF_HA   49152      // h tile A: [32][128] fp16 swizzled, 8KB
#define ROF_HB   57344      // h tile B
#define ROF_G    65536      // gates fp32 [32][68]
#define ROF_PRE  74240      // pre slice fp32 [2][32][64]
#define ROF_C1   90624
#define ROF_C2   92672
#define ROF_B2   94720
#define R_SMEM   95040

#define GS 68   // G row stride (floats)

__global__ void __launch_bounds__(256, 1) lstm_persist(
    const float* __restrict__ pre,    // [T][B][512]
    const float* __restrict__ Whh1,   // [512][128]
    const float* __restrict__ Wih2,   // [512][128]
    const float* __restrict__ Whh2,   // [512][128]
    const float* __restrict__ bih2,   // [512]
    const float* __restrict__ bhh2,   // [512]
    float* __restrict__ h2out)        // [B][128] (d_out)
{
    extern __shared__ char sm[];
    const uint32_t sb = smem_u32(sm);
    const int tid  = threadIdx.x;
    const int lane = tid & 31;
    const int wid  = tid >> 5;
    const int bb   = blockIdx.x >> 3;   // 0..15 (barrier group)
    const int ub   = blockIdx.x & 7;    // 0..7

    float* Gf  = (float*)(sm + ROF_G);
    float* prs = (float*)(sm + ROF_PRE);
    float* c1s = (float*)(sm + ROF_C1);
    float* c2s = (float*)(sm + ROF_C2);
    float* b2s = (float*)(sm + ROF_B2);

    // ---- init: weights -> fp16 smem (swizzled), zero state ----
    for (int idx = tid; idx < 64 * 128; idx += 256) {
        int j = idx >> 7;
        int k = idx & 127;
        int gcol = ((j >> 4) << 7) + (ub << 4) + (j & 15);
        uint32_t ad = (uint32_t)(j * 256 + (((k >> 3) ^ (j & 7)) << 4) + (k & 7) * 2);
        *(__half*)(sm + ROF_W1  + ad) = __float2half(Whh1[(size_t)gcol * Hn + k]);
        *(__half*)(sm + ROF_WI2 + ad) = __float2half(Wih2[(size_t)gcol * Hn + k]);
        *(__half*)(sm + ROF_WH2 + ad) = __float2half(Whh2[(size_t)gcol * Hn + k]);
    }
    if (tid < 64) {
        int gcol = ((tid >> 4) << 7) + (ub << 4) + (tid & 15);
        b2s[tid] = bih2[gcol] + bhh2[gcol];
    }
    for (int i = tid; i < 512; i += 256) { c1s[i] = 0.f; c2s[i] = 0.f; }
    for (int i = tid; i < 2048; i += 256) ((uint32_t*)(sm + ROF_HA))[i] = 0;
    {
        int u = tid & 15;
        int bl = tid >> 4;
#pragma unroll
        for (int i = 0; i < 2; i++) {
            int row = bb * 32 + bl + i * 16;
            g_h1h[row * Hn + ub * 16 + u] = __float2half(0.f);
            g_h2h[row * Hn + ub * 16 + u] = __float2half(0.f);
        }
    }
    // prefetch pre[0] slice into pres buf 0
    {
#pragma unroll
        for (int i = 0; i < 2; i++) {
            int q = 2 * tid + i;
            int b = q >> 4, ch = q & 15;
            int gcol0 = ((ch >> 2) << 7) + (ub << 4) + (ch & 3) * 4;
            const float* src = pre + ((size_t)(bb * 32 + b)) * G4 + gcol0;
            CP16(sb + ROF_PRE + (b * 64 + ch * 4) * 4, src);
        }
        CP_COMMIT();
    }
    group_barrier(bb);

    // ---- per-thread mma geometry (warp tile 16m x 16n; 2x4 warp grid) ----
    const int m_off = (wid >> 2) * 16;
    const int n_off = (wid & 3) * 16;
    const int rowA = m_off + (lane & 15);
    const uint32_t aoffA = rowA * 256;
    const int swA = rowA & 7;
    const int kuA0 = lane >> 4;
    const int rowB = n_off + (lane & 7) + ((lane >> 4) & 1) * 8;
    const uint32_t boffB = rowB * 256;
    const int swB = rowB & 7;
    const int kuB0 = (lane >> 3) & 1;

    const int u2  = tid & 15;
    const int bq  = (tid >> 4) * 2;

    auto gemm_acc = [&](uint32_t hbase, uint32_t wbase, float acc[2][4]) {
#pragma unroll
        for (int ks = 0; ks < 8; ks++) {
            uint32_t Af[4], Bf[4];
            int kuA = 2 * ks + kuA0;
            int kuB = 2 * ks + kuB0;
            ldsm4(Af, sb + hbase + aoffA + (uint32_t)(((kuA ^ swA)) << 4));
            ldsm4(Bf, sb + wbase + boffB + (uint32_t)(((kuB ^ swB)) << 4));
            mma16816h(acc[0], Af, Bf);
            mma16816h(acc[1], Af, Bf + 2);
        }
    };
    auto stage_G = [&](float acc[2][4]) {
        int r0 = m_off + (lane >> 2);
        int c0 = n_off + 2 * (lane & 3);
#pragma unroll
        for (int h = 0; h < 2; h++) {
            Gf[r0 * GS + c0 + 8 * h]           = acc[h][0];
            Gf[r0 * GS + c0 + 8 * h + 1]       = acc[h][1];
            Gf[(r0 + 8) * GS + c0 + 8 * h]     = acc[h][2];
            Gf[(r0 + 8) * GS + c0 + 8 * h + 1] = acc[h][3];
        }
    };

#pragma unroll 1
    for (int t = 0; t < Tn; t++) {
        const int p = t & 1;
        const __half* h2cur = g_h2h + p * BH;
        __half* h1nxt = g_h1h + (1 - p) * BH;
        __half* h2nxt = g_h2h + (1 - p) * BH;
        float* presc = prs + p * 2048;

        // ===== Phase A: layer-1 gates = hA @ W1^T (+ pre) =====
        CP_WAIT0();
        __syncthreads();
        {
            float acc[2][4];
#pragma unroll
            for (int q = 0; q < 2; q++)
#pragma unroll
                for (int w = 0; w < 4; w++) acc[q][w] = 0.f;
            gemm_acc(ROF_HA, ROF_W1, acc);
            stage_G(acc);
        }
        __syncthreads();
#pragma unroll
        for (int i = 0; i < 2; i++) {
            int b = bq + i;
            float iv = Gf[b * GS + u2]      + presc[b * 64 + u2];
            float fv = Gf[b * GS + 16 + u2] + presc[b * 64 + 16 + u2];
            float gv = Gf[b * GS + 32 + u2] + presc[b * 64 + 32 + u2];
            float ov = Gf[b * GS + 48 + u2] + presc[b * 64 + 48 + u2];
            int ci = b * 16 + u2;
            float cp = c1s[ci];
            float cn = sigf(fv) * cp + sigf(iv) * tanhfast(gv);
            c1s[ci] = cn;
            h1nxt[(bb * 32 + b) * Hn + ub * 16 + u2] = __float2half(sigf(ov) * tanhfast(cn));
        }
        group_barrier(bb);

        // ===== Phase B: layer-2 gates = h1new @ Wi2^T + h2 @ Wh2^T + b2 =====
        {
#pragma unroll
            for (int i = 0; i < 2; i++) {
                int q = 2 * tid + i;
                int rr = q >> 4, ku = q & 15;
                uint32_t doff = (uint32_t)(rr * 256 + ((ku ^ (rr & 7)) << 4));
                CP16(sb + ROF_HA + doff, h1nxt + (bb * 32 + rr) * Hn + ku * 8);
                CP16(sb + ROF_HB + doff, h2cur + (bb * 32 + rr) * Hn + ku * 8);
            }
            CP_COMMIT();
        }
        if (t < Tn - 1) {   // prefetch pre[t+1], stays in flight through phase B
#pragma unroll
            for (int i = 0; i < 2; i++) {
                int q = 2 * tid + i;
                int b = q >> 4, ch = q & 15;
                int gcol0 = ((ch >> 2) << 7) + (ub << 4) + (ch & 3) * 4;
                const float* src = pre + ((size_t)(t + 1) * Bn + bb * 32 + b) * G4 + gcol0;
                CP16(sb + ROF_PRE + ((1 - p) * 2048 + b * 64 + ch * 4) * 4, src);
            }
            CP_COMMIT();
            CP_WAIT1();
        } else {
            CP_WAIT0();
        }
        __syncthreads();
        {
            float acc[2][4];
#pragma unroll
            for (int q = 0; q < 2; q++)
#pragma unroll
                for (int w = 0; w < 4; w++) acc[q][w] = 0.f;
            gemm_acc(ROF_HA, ROF_WI2, acc);
            gemm_acc(ROF_HB, ROF_WH2, acc);
            stage_G(acc);
        }
        __syncthreads();
#pragma unroll
        for (int i = 0; i < 2; i++) {
            int b = bq + i;
            float iv = Gf[b * GS + u2]      + b2s[u2];
            float fv = Gf[b * GS + 16 + u2] + b2s[16 + u2];
            float gv = Gf[b * GS + 32 + u2] + b2s[32 + u2];
            float ov = Gf[b * GS + 48 + u2] + b2s[48 + u2];
            int ci = b * 16 + u2;
            float cp = c2s[ci];
            float cn = sigf(fv) * cp + sigf(iv) * tanhfast(gv);
            c2s[ci] = cn;
            float hn = sigf(ov) * tanhfast(cn);
            h2nxt[(bb * 32 + b) * Hn + ub * 16 + u2] = __float2half(hn);
            if (t == Tn - 1)
                h2out[(bb * 32 + b) * Hn + ub * 16 + u2] = hn;
        }
        __syncthreads();
    }
}

// -------- launch --------
extern "C" void kernel_launch(void* const* d_in, const int* in_sizes, int n_in,
                              void* d_out, int out_size) {
    const float* feats = (const float*)d_in[0];
    const float* Wih1  = (const float*)d_in[1];
    const float* Whh1  = (const float*)d_in[2];
    const float* bih1  = (const float*)d_in[3];
    const float* bhh1  = (const float*)d_in[4];
    const float* Wih2  = (const float*)d_in[5];
    const float* Whh2  = (const float*)d_in[6];
    const float* bih2  = (const float*)d_in[7];
    const float* bhh2  = (const float*)d_in[8];

    float* pre;
    __half *Ah, *Wh;
    cudaGetSymbolAddress((void**)&pre, g_pre);
    cudaGetSymbolAddress((void**)&Ah,  g_Ah);
    cudaGetSymbolAddress((void**)&Wh,  g_Wh);

    static int attr_set = 0;
    if (!attr_set) {
        cudaFuncSetAttribute(lstm_persist,
                             cudaFuncAttributeMaxDynamicSharedMemorySize,
                             R_SMEM);
        attr_set = 1;
    }

    // fp32 -> fp16 staging
    cvt_fp16_kernel<<<4096, 256>>>(feats, Ah, (Bn * Tn * Dn) / 8);
    cvt_fp16_kernel<<<256, 256>>>(Wih1, Wh, (G4 * Dn) / 8);

    // pre = feats @ Wih1^T + bih1 + bhh1
    gemm_pre_mma<<<dim3(4, 512), 256>>>(Ah, Wh, bih1, bhh1, pre);

    lstm_persist<<<128, 256, R_SMEM>>>(
        pre, Whh1, Wih2, Whh2, bih2, bhh2, (float*)d_out);
}